// round 11
// baseline (speedup 1.0000x reference)
#include <cuda_runtime.h>
#include <cuda_bf16.h>
#include <math.h>
#include <stdint.h>

// Problem constants
#define Bn   32
#define Ln   4096
#define Hn   256
#define N2n  32
#define NLn  4
#define DOUTn 8

// ---------------- scratch (device globals; no allocation allowed) ----------------
__device__ float    g_h[(size_t)Bn * Hn * Ln];     // 128 MB  current hidden (B,H,L)
__device__ uint32_t g_y[(size_t)Bn * Hn * Ln];     // 128 MB  tf32 bits of gelu(ssm) (B,H,L)
__device__ float    g_z[(size_t)Bn * 2 * Hn * Ln]; // 256 MB  GEMM output (B,2H,L)
__device__ float    g_par[NLn * 4 * Hn * N2n];     // w_re,w_im,cd_re,cd_im (2x folded)
__device__ uint32_t g_wfrag[NLn * 512 * 256];      // W as tf32 bits, MMA-fragment order
__device__ float    g_pool[Bn * Hn];
// Toeplitz-scan matrices, per (layer,h): 32x32 each, row-major
__device__ float    g_T  [NLn * Hn * 1024];
__device__ float    g_M1 [NLn * Hn * 1024];
__device__ float    g_M2 [NLn * Hn * 1024];
__device__ float    g_Gre[NLn * Hn * 1024];
__device__ float    g_Gim[NLn * Hn * 1024];
__device__ float    g_w32re[NLn * Hn * 32];
__device__ float    g_w32im[NLn * Hn * 32];

// ---------------- helpers ----------------
__device__ __forceinline__ float gelu_tanh(float x) {
    float x3 = x * x * x;
    float t = tanhf(0.7978845608028654f * (x + 0.044715f * x3));
    return 0.5f * x * (1.0f + t);
}
__device__ __forceinline__ float sigmoidf_(float x) {
    return 1.0f / (1.0f + expf(-x));
}
__device__ __forceinline__ uint32_t to_tf32(float x) {
    uint32_t r;
    asm("cvt.rna.tf32.f32 %0, %1;" : "=r"(r) : "f"(x));
    return r;
}

// mma.sync m16n8k8 tf32: D = A@B + D   (A,B as raw b32 tf32 bit patterns)
__device__ __forceinline__ void mma_tf32(float (&d)[4], const uint4& a, const uint2& b) {
    asm volatile(
        "mma.sync.aligned.m16n8k8.row.col.f32.tf32.tf32.f32 "
        "{%0,%1,%2,%3}, {%4,%5,%6,%7}, {%8,%9}, {%0,%1,%2,%3};\n"
        : "+f"(d[0]), "+f"(d[1]), "+f"(d[2]), "+f"(d[3])
        : "r"(a.x), "r"(a.y), "r"(a.z), "r"(a.w), "r"(b.x), "r"(b.y));
}

// ---------------- 0a. precompute discretized SSM params ----------------
__global__ void precompute_kernel(const float* __restrict__ log_dt,
                                  const float* __restrict__ C_re,
                                  const float* __restrict__ C_im,
                                  const float* __restrict__ log_A_real,
                                  const float* __restrict__ A_imag) {
    int idx = blockIdx.x * blockDim.x + threadIdx.x;      // NL*H*N2
    if (idx >= NLn * Hn * N2n) return;
    int i = idx / (Hn * N2n);
    int rem = idx % (Hn * N2n);
    int h = rem / N2n;

    float dt = expf(log_dt[i * Hn + h]);
    float Are = -expf(log_A_real[idx]);
    float Aim = A_imag[idx];
    float dre = Are * dt, dim = Aim * dt;
    float e = expf(dre);
    float w_re = e * cosf(dim);
    float w_im = e * sinf(dim);
    float inv = 1.0f / (Are * Are + Aim * Aim);
    float nre = w_re - 1.0f, nim = w_im;
    float fre = (nre * Are + nim * Aim) * inv;
    float fim = (nim * Are - nre * Aim) * inv;
    float cre = C_re[idx], cim = C_im[idx];
    float cd_re = cre * fre - cim * fim;
    float cd_im = cre * fim + cim * fre;

    int base = ((i * 4 + 0) * Hn + h) * N2n + (idx % N2n);
    int stride = Hn * N2n;
    g_par[base + 0 * stride] = w_re;
    g_par[base + 1 * stride] = w_im;
    g_par[base + 2 * stride] = 2.0f * cd_re;   // fold the 2x into C
    g_par[base + 3 * stride] = 2.0f * cd_im;
}

// ---------------- 0b. build Toeplitz-scan matrices per (layer,h) ----------------
// One warp per (layer,h). lane = state n.
__global__ __launch_bounds__(256) void precompute2_kernel(const float* __restrict__ Dmat) {
    __shared__ float kbuf[8][33];
    int warp = threadIdx.x >> 5, lane = threadIdx.x & 31;
    int idx = blockIdx.x * 8 + warp;           // 0..NL*Hn-1
    if (idx >= NLn * Hn) return;
    int l = idx >> 8, h = idx & 255;

    int pstride = Hn * N2n;
    int pbase = ((l * 4) * Hn + h) * N2n + lane;
    float wre = g_par[pbase + 0 * pstride];
    float wim = g_par[pbase + 1 * pstride];
    float cre = g_par[pbase + 2 * pstride];    // 2*Cd
    float cim = g_par[pbase + 3 * pstride];
    float Dh = Dmat[l * Hn + h];

    size_t mbase = (size_t)idx * 1024;

    float pre = 1.0f, pim = 0.0f;              // w^0
    for (int d = 0; d <= 32; ++d) {
        float m1 = cre * pre - cim * pim;        // Re(Cd w^d)  (per lane n)
        float m2 = -(cre * pim + cim * pre);     // -Im(Cd w^d)
        if (d >= 1) {
            g_M1[mbase + (size_t)(d - 1) * 32 + lane] = m1;   // M1[t=d-1][n]
            g_M2[mbase + (size_t)(d - 1) * 32 + lane] = m2;
        }
        if (d < 32) {
            // K[d] = sum_n m1
            float kd = m1;
#pragma unroll
            for (int off = 16; off > 0; off >>= 1)
                kd += __shfl_xor_sync(0xffffffffu, kd, off);
            if (lane == 0) kbuf[warp][d] = kd;
            // G[n][31-d] = w^d
            g_Gre[mbase + (size_t)lane * 32 + (31 - d)] = pre;
            g_Gim[mbase + (size_t)lane * 32 + (31 - d)] = pim;
        }
        if (d == 32) {
            g_w32re[(size_t)idx * 32 + lane] = pre;   // w^32
            g_w32im[(size_t)idx * 32 + lane] = pim;
        }
        float npre = pre * wre - pim * wim;
        float npim = pre * wim + pim * wre;
        pre = npre; pim = npim;
    }
    __syncwarp();
    // T[t][s] = K[t-s] (t>s), K[0]+Dh (t==s), 0 (t<s)
    for (int e = lane; e < 1024; e += 32) {
        int t = e >> 5, s = e & 31;
        float v = 0.0f;
        if (t > s) v = kbuf[warp][t - s];
        else if (t == s) v = kbuf[warp][0] + Dh;
        g_T[mbase + e] = v;
    }
}

// ---------------- 0c. pre-permute W into tf32 MMA-fragment order ----------------
__global__ void wfrag_kernel(const float* __restrict__ out_w) {
    int idx = blockIdx.x * blockDim.x + threadIdx.x;    // NL*512*256
    if (idx >= NLn * 512 * 256) return;
    int layer = idx / (512 * 256);
    int rem = idx % (512 * 256);
    int m = rem / 256;
    int k = rem % 256;
    uint32_t val = to_tf32(out_w[idx]);

    int kc = k >> 4;
    int kk = (k >> 3) & 1;
    int tig = k & 3;
    int half = (k >> 2) & 1;
    int mt = m >> 4;
    int g = m & 7;
    int r8 = (m >> 3) & 1;
    int lane = 4 * g + tig;
    int i4 = r8 + 2 * half;
    int dst = (((kc * 32 + mt) * 2 + kk) * 32 + lane) * 4 + i4;
    g_wfrag[layer * 131072 + dst] = val;
}

// ---------------- 2. Toeplitz-chunk SSM scan on tensor cores ----------------
// Block: one h, 4 warps = 4 b's. grid = 256h x 8 b-groups = 2048 blocks, 128 thr.
__global__ __launch_bounds__(128) void scan_tc_kernel(const float* __restrict__ x,
                                                      const float* __restrict__ enc_w,
                                                      const float* __restrict__ enc_b,
                                                      int layer) {
    __shared__ uint32_t Tm [32][33];
    __shared__ uint32_t M1m[32][33];
    __shared__ uint32_t M2m[32][33];
    __shared__ uint32_t Grm[32][33];
    __shared__ uint32_t Gim[32][33];
    __shared__ uint32_t Us [4][32][9];   // u tile tf32 [s][c]
    __shared__ float    Sre[4][32][9];   // S output / reused as y tile
    __shared__ float    Sim[4][32][9];
    __shared__ uint32_t Pre[4][32][9];   // s_prev tf32 bits [n][c]
    __shared__ uint32_t Pim[4][32][9];

    int tid = threadIdx.x;
    int warp = tid >> 5, lane = tid & 31;
    int g = lane >> 2, tig = lane & 3;
    int h = blockIdx.x >> 3;
    int b = (blockIdx.x & 7) * 4 + warp;

    // load per-h matrices (tf32-converted)
    size_t mbase = (size_t)(layer * Hn + h) * 1024;
    for (int e = tid; e < 1024; e += 128) {
        int r = e >> 5, c = e & 31;
        Tm [r][c] = to_tf32(g_T  [mbase + e]);
        M1m[r][c] = to_tf32(g_M1 [mbase + e]);
        M2m[r][c] = to_tf32(g_M2 [mbase + e]);
        Grm[r][c] = to_tf32(g_Gre[mbase + e]);
        Gim[r][c] = to_tf32(g_Gim[mbase + e]);
    }
    __syncthreads();

    float w32re_ = g_w32re[(size_t)(layer * Hn + h) * 32 + lane];
    float w32im_ = g_w32im[(size_t)(layer * Hn + h) * 32 + lane];

    size_t rowoff = ((size_t)b * Hn + h) * Ln;
    float* hrow = g_h + rowoff;
    uint32_t* yrow = g_y + rowoff;
    const float* xrow = x + (size_t)b * Ln;
    bool l0fuse = (layer == 0);
    float ew = l0fuse ? enc_w[h] : 0.0f;
    float eb = l0fuse ? enc_b[h] : 0.0f;

    float sre = 0.0f, sim = 0.0f;

    for (int gr = 0; gr < 16; ++gr) {
        int base_l = gr * 256;
        // ---- fill u tile [s=lane][c=i] ----
        if (l0fuse) {
#pragma unroll
            for (int i = 0; i < 8; ++i) {
                float v = fmaf(xrow[base_l + i * 32 + lane], ew, eb);
                hrow[base_l + i * 32 + lane] = v;
                Us[warp][lane][i] = to_tf32(v);
            }
        } else {
#pragma unroll
            for (int i = 0; i < 8; ++i)
                Us[warp][lane][i] = to_tf32(hrow[base_l + i * 32 + lane]);
        }
        __syncwarp();

        // ---- B fragments from u tile ----
        uint2 bu[4];
#pragma unroll
        for (int k8 = 0; k8 < 4; ++k8) {
            bu[k8].x = Us[warp][k8 * 8 + tig][g];
            bu[k8].y = Us[warp][k8 * 8 + tig + 4][g];
        }

        // ---- S = Gre@U, Gim@U ----
        float fre[2][4], fim[2][4];
#pragma unroll
        for (int mt = 0; mt < 2; ++mt)
#pragma unroll
            for (int r = 0; r < 4; ++r) { fre[mt][r] = 0.0f; fim[mt][r] = 0.0f; }
#pragma unroll
        for (int mt = 0; mt < 2; ++mt) {
            int mr = mt * 16;
#pragma unroll
            for (int k8 = 0; k8 < 4; ++k8) {
                int kb = k8 * 8;
                uint4 ar = make_uint4(Grm[mr + g][kb + tig], Grm[mr + g + 8][kb + tig],
                                      Grm[mr + g][kb + tig + 4], Grm[mr + g + 8][kb + tig + 4]);
                mma_tf32(fre[mt], ar, bu[k8]);
                uint4 ai = make_uint4(Gim[mr + g][kb + tig], Gim[mr + g + 8][kb + tig],
                                      Gim[mr + g][kb + tig + 4], Gim[mr + g + 8][kb + tig + 4]);
                mma_tf32(fim[mt], ai, bu[k8]);
            }
        }
#pragma unroll
        for (int mt = 0; mt < 2; ++mt) {
            int mr = mt * 16;
            Sre[warp][mr + g][2 * tig]     = fre[mt][0];
            Sre[warp][mr + g][2 * tig + 1] = fre[mt][1];
            Sre[warp][mr + g + 8][2 * tig]     = fre[mt][2];
            Sre[warp][mr + g + 8][2 * tig + 1] = fre[mt][3];
            Sim[warp][mr + g][2 * tig]     = fim[mt][0];
            Sim[warp][mr + g][2 * tig + 1] = fim[mt][1];
            Sim[warp][mr + g + 8][2 * tig]     = fim[mt][2];
            Sim[warp][mr + g + 8][2 * tig + 1] = fim[mt][3];
        }
        __syncwarp();

        // ---- sequential scan over 8 chunks (lane = state n) ----
#pragma unroll
        for (int c = 0; c < 8; ++c) {
            Pre[warp][lane][c] = to_tf32(sre);
            Pim[warp][lane][c] = to_tf32(sim);
            float S_re = Sre[warp][lane][c];
            float S_im = Sim[warp][lane][c];
            float nre = fmaf(w32re_, sre, fmaf(-w32im_, sim, S_re));
            float nim = fmaf(w32re_, sim, fmaf(w32im_, sre, S_im));
            sre = nre; sim = nim;
        }
        __syncwarp();

        // ---- Y = T@U + M1@Sprev_re + M2@Sprev_im ----
        float yf[2][4];
#pragma unroll
        for (int mt = 0; mt < 2; ++mt)
#pragma unroll
            for (int r = 0; r < 4; ++r) yf[mt][r] = 0.0f;
        uint2 bp[4], bq[4];
#pragma unroll
        for (int k8 = 0; k8 < 4; ++k8) {
            bp[k8].x = Pre[warp][k8 * 8 + tig][g];
            bp[k8].y = Pre[warp][k8 * 8 + tig + 4][g];
            bq[k8].x = Pim[warp][k8 * 8 + tig][g];
            bq[k8].y = Pim[warp][k8 * 8 + tig + 4][g];
        }
#pragma unroll
        for (int mt = 0; mt < 2; ++mt) {
            int mr = mt * 16;
#pragma unroll
            for (int k8 = 0; k8 < 4; ++k8) {
                int kb = k8 * 8;
                uint4 at = make_uint4(Tm[mr + g][kb + tig], Tm[mr + g + 8][kb + tig],
                                      Tm[mr + g][kb + tig + 4], Tm[mr + g + 8][kb + tig + 4]);
                mma_tf32(yf[mt], at, bu[k8]);
                uint4 a1 = make_uint4(M1m[mr + g][kb + tig], M1m[mr + g + 8][kb + tig],
                                      M1m[mr + g][kb + tig + 4], M1m[mr + g + 8][kb + tig + 4]);
                mma_tf32(yf[mt], a1, bp[k8]);
                uint4 a2 = make_uint4(M2m[mr + g][kb + tig], M2m[mr + g + 8][kb + tig],
                                      M2m[mr + g][kb + tig + 4], M2m[mr + g + 8][kb + tig + 4]);
                mma_tf32(yf[mt], a2, bq[k8]);
            }
        }
        // ---- stage Y to smem (reuse Sre), then gelu + store ----
#pragma unroll
        for (int mt = 0; mt < 2; ++mt) {
            int mr = mt * 16;
            Sre[warp][mr + g][2 * tig]     = yf[mt][0];
            Sre[warp][mr + g][2 * tig + 1] = yf[mt][1];
            Sre[warp][mr + g + 8][2 * tig]     = yf[mt][2];
            Sre[warp][mr + g + 8][2 * tig + 1] = yf[mt][3];
        }
        __syncwarp();
#pragma unroll
        for (int i = 0; i < 8; ++i) {
            float v = Sre[warp][lane][i];      // y[t=lane][c=i]
            yrow[base_l + i * 32 + lane] = to_tf32(gelu_tanh(v));
        }
        __syncwarp();
    }
}

// ---------------- 3. tf32 tensor-core GEMM, fragment-ordered A ----------------
__global__ __launch_bounds__(256) void gemm_tc_kernel(const float* __restrict__ out_b,
                                                      int layer) {
    __shared__ uint32_t As[8192];
    __shared__ uint32_t Bs[16][132];

    int b = blockIdx.z;
    const uint32_t* Yb = g_y + (size_t)b * Hn * Ln;
    float* Z = g_z + (size_t)b * 2 * Hn * Ln;
    const uint32_t* Wf = g_wfrag + layer * 131072;
    const float* obl = out_b + layer * 2 * Hn;

    int n0 = blockIdx.x * 128;
    int m0 = blockIdx.y * 128;
    int mt0 = m0 >> 4;

    int tid = threadIdx.x;
    int warp = tid >> 5, lane = tid & 31;
    int wm = warp >> 2;
    int wn = warp & 3;
    int g = lane >> 2, tig = lane & 3;

    float acc[4][4][4];
#pragma unroll
    for (int mt = 0; mt < 4; ++mt)
#pragma unroll
        for (int nt = 0; nt < 4; ++nt)
#pragma unroll
            for (int r = 0; r < 4; ++r) acc[mt][nt][r] = 0.0f;

    uint4 pa[2], pb[2];
    {
        const uint4* srcA = reinterpret_cast<const uint4*>(Wf + (0 * 32 + mt0) * 256);
        pa[0] = srcA[tid];
        pa[1] = srcA[tid + 256];
#pragma unroll
        for (int j = 0; j < 2; ++j) {
            int idx4 = tid + j * 256;
            int r = idx4 >> 5, c4 = idx4 & 31;
            pb[j] = *reinterpret_cast<const uint4*>(&Yb[(size_t)r * Ln + n0 + c4 * 4]);
        }
    }

    for (int kc = 0; kc < 16; ++kc) {
        reinterpret_cast<uint4*>(As)[tid] = pa[0];
        reinterpret_cast<uint4*>(As)[tid + 256] = pa[1];
#pragma unroll
        for (int j = 0; j < 2; ++j) {
            int idx4 = tid + j * 256;
            int r = idx4 >> 5, c4 = idx4 & 31;
            *reinterpret_cast<uint4*>(&Bs[r][c4 * 4]) = pb[j];
        }
        __syncthreads();

        if (kc + 1 < 16) {
            const uint4* srcA = reinterpret_cast<const uint4*>(Wf + ((kc + 1) * 32 + mt0) * 256);
            pa[0] = srcA[tid];
            pa[1] = srcA[tid + 256];
#pragma unroll
            for (int j = 0; j < 2; ++j) {
                int idx4 = tid + j * 256;
                int r = idx4 >> 5, c4 = idx4 & 31;
                pb[j] = *reinterpret_cast<const uint4*>(
                    &Yb[(size_t)((kc + 1) * 16 + r) * Ln + n0 + c4 * 4]);
            }
        }

#pragma unroll
        for (int kk = 0; kk < 2; ++kk) {
            int k8 = kk * 8;
            uint4 afr[4];
#pragma unroll
            for (int mt = 0; mt < 4; ++mt)
                afr[mt] = *reinterpret_cast<const uint4*>(
                    &As[(((wm * 4 + mt) * 2 + kk) * 32 + lane) * 4]);
            uint2 bfr[4];
#pragma unroll
            for (int nt = 0; nt < 4; ++nt) {
                int ncol = wn * 32 + nt * 8;
                bfr[nt].x = Bs[k8 + tig][ncol + g];
                bfr[nt].y = Bs[k8 + tig + 4][ncol + g];
            }
#pragma unroll
            for (int mt = 0; mt < 4; ++mt)
#pragma unroll
                for (int nt = 0; nt < 4; ++nt)
                    mma_tf32(acc[mt][nt], afr[mt], bfr[nt]);
        }
        __syncthreads();
    }

#pragma unroll
    for (int mt = 0; mt < 4; ++mt) {
        int m = m0 + wm * 64 + mt * 16 + g;
        float bias0 = obl[m];
        float bias1 = obl[m + 8];
#pragma unroll
        for (int nt = 0; nt < 4; ++nt) {
            int n = n0 + wn * 32 + nt * 8 + 2 * tig;
            float2 v0 = make_float2(acc[mt][nt][0] + bias0, acc[mt][nt][1] + bias0);
            float2 v1 = make_float2(acc[mt][nt][2] + bias1, acc[mt][nt][3] + bias1);
            *reinterpret_cast<float2*>(&Z[(size_t)m * Ln + n]) = v0;
            *reinterpret_cast<float2*>(&Z[(size_t)(m + 8) * Ln + n]) = v1;
        }
    }
}

// ---------------- 4. GLU + residual + LayerNorm (in-place on g_h) ----------------
__global__ __launch_bounds__(256) void glu_ln_kernel(const float* __restrict__ ln_w_all,
                                                     const float* __restrict__ ln_b_all,
                                                     int layer) {
    int b = blockIdx.y;
    int l0 = blockIdx.x * 32;
    const float* Z = g_z + (size_t)b * 2 * Hn * Ln;
    float* Hb = g_h + (size_t)b * Hn * Ln;
    const float* lnw = ln_w_all + layer * Hn;
    const float* lnb = ln_b_all + layer * Hn;

    __shared__ float t[Hn][33];
    __shared__ float mu_s[32], rs_s[32];

    int tx = threadIdx.x & 31;
    int ty = threadIdx.x >> 5;

    for (int oo = 0; oo < Hn; oo += 8) {
        int o = oo + ty;
        float a = Z[(size_t)o * Ln + l0 + tx];
        float g = Z[(size_t)(o + Hn) * Ln + l0 + tx];
        float hold = Hb[(size_t)o * Ln + l0 + tx];
        t[o][tx] = a * sigmoidf_(g) + hold;
    }
    __syncthreads();

    for (int c = ty; c < 32; c += 8) {
        float s = 0.0f, s2 = 0.0f;
#pragma unroll
        for (int k = 0; k < 8; ++k) {
            float v = t[tx + 32 * k][c];
            s += v; s2 += v * v;
        }
#pragma unroll
        for (int off = 16; off > 0; off >>= 1) {
            s += __shfl_xor_sync(0xffffffffu, s, off);
            s2 += __shfl_xor_sync(0xffffffffu, s2, off);
        }
        if (tx == 0) {
            float mu = s * (1.0f / Hn);
            float var = s2 * (1.0f / Hn) - mu * mu;
            mu_s[c] = mu;
            rs_s[c] = rsqrtf(var + 1e-5f);
        }
    }
    __syncthreads();

    for (int oo = 0; oo < Hn; oo += 8) {
        int o = oo + ty;
        float v = (t[o][tx] - mu_s[tx]) * rs_s[tx] * lnw[o] + lnb[o];
        Hb[(size_t)o * Ln + l0 + tx] = v;
    }
}

// ---------------- 5. mean pool over L ----------------
__global__ void pool_kernel() {
    int row = blockIdx.x;  // b*H+h
    const float* p = g_h + (size_t)row * Ln;
    float s = 0.0f;
    for (int l = threadIdx.x; l < Ln; l += 256) s += p[l];
    __shared__ float red[256];
    red[threadIdx.x] = s;
    __syncthreads();
    for (int off = 128; off > 0; off >>= 1) {
        if (threadIdx.x < off) red[threadIdx.x] += red[threadIdx.x + off];
        __syncthreads();
    }
    if (threadIdx.x == 0) g_pool[row] = red[0] * (1.0f / Ln);
}

// ---------------- 6. decoder ----------------
__global__ void decode_kernel(const float* __restrict__ dec_w,
                              const float* __restrict__ dec_b,
                              float* __restrict__ out) {
    int idx = threadIdx.x;      // 256 = B*DOUT
    int b = idx >> 3, d = idx & 7;
    float s = dec_b[d];
    for (int h = 0; h < Hn; ++h)
        s += g_pool[b * Hn + h] * dec_w[d * Hn + h];
    out[idx] = sigmoidf_(s);
}

// ---------------- launch ----------------
extern "C" void kernel_launch(void* const* d_in, const int* in_sizes, int n_in,
                              void* d_out, int out_size) {
    const float* x          = (const float*)d_in[0];
    const float* enc_w      = (const float*)d_in[1];
    const float* enc_b      = (const float*)d_in[2];
    const float* log_dt     = (const float*)d_in[3];
    const float* C_re       = (const float*)d_in[4];
    const float* C_im       = (const float*)d_in[5];
    const float* log_A_real = (const float*)d_in[6];
    const float* A_imag     = (const float*)d_in[7];
    const float* D          = (const float*)d_in[8];
    const float* out_w      = (const float*)d_in[9];
    const float* out_b      = (const float*)d_in[10];
    const float* ln_w       = (const float*)d_in[11];
    const float* ln_b       = (const float*)d_in[12];
    const float* dec_w      = (const float*)d_in[13];
    const float* dec_b      = (const float*)d_in[14];
    float* out = (float*)d_out;

    precompute_kernel<<<(NLn * Hn * N2n + 255) / 256, 256>>>(log_dt, C_re, C_im,
                                                             log_A_real, A_imag);
    precompute2_kernel<<<(NLn * Hn) / 8, 256>>>(D);
    wfrag_kernel<<<(NLn * 512 * 256 + 255) / 256, 256>>>(out_w);

    dim3 ggrid(Ln / 128, 512 / 128, Bn);
    dim3 egrid(Ln / 32, Bn);

    for (int i = 0; i < NLn; ++i) {
        scan_tc_kernel<<<Hn * 8, 128>>>(x, enc_w, enc_b, i);
        gemm_tc_kernel<<<ggrid, 256>>>(out_b, i);
        glu_ln_kernel<<<egrid, 256>>>(ln_w, ln_b, i);
    }

    pool_kernel<<<Bn * Hn, 256>>>();
    decode_kernel<<<1, 256>>>(dec_w, dec_b, out);
}

// round 12
// speedup vs baseline: 1.3785x; 1.3785x over previous
#include <cuda_runtime.h>
#include <cuda_bf16.h>
#include <math.h>
#include <stdint.h>

// Problem constants
#define Bn   32
#define Ln   4096
#define Hn   256
#define N2n  32
#define NLn  4
#define DOUTn 8

// ---------------- scratch (device globals; no allocation allowed) ----------------
__device__ float    g_h[(size_t)Bn * Hn * Ln];     // 128 MB  current hidden (B,H,L)
__device__ uint32_t g_y[(size_t)Bn * Hn * Ln];     // 128 MB  tf32 bits of gelu(ssm) (B,H,L)
__device__ float    g_z[(size_t)Bn * 2 * Hn * Ln]; // 256 MB  GEMM output (B,2H,L)
__device__ float    g_par[NLn * 4 * Hn * N2n];     // w_re,w_im,cd_re,cd_im (2x folded)
__device__ uint32_t g_wfrag[NLn * 512 * 256];      // W as tf32 bits, MMA-fragment order
__device__ float    g_pool[Bn * Hn];
// Toeplitz-scan matrices, per (layer,h): 32x32 each, row-major (fp32 staging)
__device__ float    g_T  [NLn * Hn * 1024];
__device__ float    g_M1 [NLn * Hn * 1024];
__device__ float    g_M2 [NLn * Hn * 1024];
__device__ float    g_Gre[NLn * Hn * 1024];
__device__ float    g_Gim[NLn * Hn * 1024];
// fragment-ordered tf32 versions: [mt(2)][k8(4)][lane(32)][4]
__device__ uint32_t g_Tf  [NLn * Hn * 1024];
__device__ uint32_t g_M1f [NLn * Hn * 1024];
__device__ uint32_t g_M2f [NLn * Hn * 1024];
__device__ uint32_t g_Grf [NLn * Hn * 1024];
__device__ uint32_t g_Gif [NLn * Hn * 1024];
__device__ float    g_w32re[NLn * Hn * 32];
__device__ float    g_w32im[NLn * Hn * 32];

// ---------------- helpers ----------------
__device__ __forceinline__ float gelu_tanh(float x) {
    float x3 = x * x * x;
    float t = tanhf(0.7978845608028654f * (x + 0.044715f * x3));
    return 0.5f * x * (1.0f + t);
}
__device__ __forceinline__ float sigmoidf_(float x) {
    return 1.0f / (1.0f + expf(-x));
}
__device__ __forceinline__ uint32_t to_tf32(float x) {
    uint32_t r;
    asm("cvt.rna.tf32.f32 %0, %1;" : "=r"(r) : "f"(x));
    return r;
}

// mma.sync m16n8k8 tf32: D = A@B + D   (A,B as raw b32 tf32 bit patterns)
__device__ __forceinline__ void mma_tf32(float (&d)[4], const uint4& a, const uint2& b) {
    asm volatile(
        "mma.sync.aligned.m16n8k8.row.col.f32.tf32.tf32.f32 "
        "{%0,%1,%2,%3}, {%4,%5,%6,%7}, {%8,%9}, {%0,%1,%2,%3};\n"
        : "+f"(d[0]), "+f"(d[1]), "+f"(d[2]), "+f"(d[3])
        : "r"(a.x), "r"(a.y), "r"(a.z), "r"(a.w), "r"(b.x), "r"(b.y));
}

// ---------------- 0a. precompute discretized SSM params ----------------
__global__ void precompute_kernel(const float* __restrict__ log_dt,
                                  const float* __restrict__ C_re,
                                  const float* __restrict__ C_im,
                                  const float* __restrict__ log_A_real,
                                  const float* __restrict__ A_imag) {
    int idx = blockIdx.x * blockDim.x + threadIdx.x;      // NL*H*N2
    if (idx >= NLn * Hn * N2n) return;
    int i = idx / (Hn * N2n);
    int rem = idx % (Hn * N2n);
    int h = rem / N2n;

    float dt = expf(log_dt[i * Hn + h]);
    float Are = -expf(log_A_real[idx]);
    float Aim = A_imag[idx];
    float dre = Are * dt, dim = Aim * dt;
    float e = expf(dre);
    float w_re = e * cosf(dim);
    float w_im = e * sinf(dim);
    float inv = 1.0f / (Are * Are + Aim * Aim);
    float nre = w_re - 1.0f, nim = w_im;
    float fre = (nre * Are + nim * Aim) * inv;
    float fim = (nim * Are - nre * Aim) * inv;
    float cre = C_re[idx], cim = C_im[idx];
    float cd_re = cre * fre - cim * fim;
    float cd_im = cre * fim + cim * fre;

    int base = ((i * 4 + 0) * Hn + h) * N2n + (idx % N2n);
    int stride = Hn * N2n;
    g_par[base + 0 * stride] = w_re;
    g_par[base + 1 * stride] = w_im;
    g_par[base + 2 * stride] = 2.0f * cd_re;   // fold the 2x into C
    g_par[base + 3 * stride] = 2.0f * cd_im;
}

// ---------------- 0b. build Toeplitz-scan matrices per (layer,h) ----------------
__global__ __launch_bounds__(256) void precompute2_kernel(const float* __restrict__ Dmat) {
    __shared__ float kbuf[8][33];
    int warp = threadIdx.x >> 5, lane = threadIdx.x & 31;
    int idx = blockIdx.x * 8 + warp;           // 0..NL*Hn-1
    if (idx >= NLn * Hn) return;
    int l = idx >> 8, h = idx & 255;

    int pstride = Hn * N2n;
    int pbase = ((l * 4) * Hn + h) * N2n + lane;
    float wre = g_par[pbase + 0 * pstride];
    float wim = g_par[pbase + 1 * pstride];
    float cre = g_par[pbase + 2 * pstride];    // 2*Cd
    float cim = g_par[pbase + 3 * pstride];
    float Dh = Dmat[l * Hn + h];

    size_t mbase = (size_t)idx * 1024;

    float pre = 1.0f, pim = 0.0f;              // w^0
    for (int d = 0; d <= 32; ++d) {
        float m1 = cre * pre - cim * pim;        // Re(Cd w^d)
        float m2 = -(cre * pim + cim * pre);     // -Im(Cd w^d)
        if (d >= 1) {
            g_M1[mbase + (size_t)(d - 1) * 32 + lane] = m1;   // M1[t=d-1][n]
            g_M2[mbase + (size_t)(d - 1) * 32 + lane] = m2;
        }
        if (d < 32) {
            float kd = m1;
#pragma unroll
            for (int off = 16; off > 0; off >>= 1)
                kd += __shfl_xor_sync(0xffffffffu, kd, off);
            if (lane == 0) kbuf[warp][d] = kd;
            g_Gre[mbase + (size_t)lane * 32 + (31 - d)] = pre;
            g_Gim[mbase + (size_t)lane * 32 + (31 - d)] = pim;
        }
        if (d == 32) {
            g_w32re[(size_t)idx * 32 + lane] = pre;
            g_w32im[(size_t)idx * 32 + lane] = pim;
        }
        float npre = pre * wre - pim * wim;
        float npim = pre * wim + pim * wre;
        pre = npre; pim = npim;
    }
    __syncwarp();
    for (int e = lane; e < 1024; e += 32) {
        int t = e >> 5, s = e & 31;
        float v = 0.0f;
        if (t > s) v = kbuf[warp][t - s];
        else if (t == s) v = kbuf[warp][0] + Dh;
        g_T[mbase + e] = v;
    }
}

// ---------------- 0c. fragment-order the scan matrices (tf32 bits) ----------------
// elem (t,s) -> dst ((mt*4+k8)*32 + lane)*4 + i  within the 1024-word block
__global__ void fragmat_kernel() {
    int idx = blockIdx.x * blockDim.x + threadIdx.x;   // NL*Hn*1024
    if (idx >= NLn * Hn * 1024) return;
    int blk = idx >> 10;           // (layer,h)
    int e = idx & 1023;
    int t = e >> 5, s = e & 31;
    int mt = t >> 4;
    int g = t & 7;
    int r8 = (t >> 3) & 1;
    int k8 = s >> 3;
    int tig = s & 3;
    int half = (s >> 2) & 1;
    int lane = 4 * g + tig;
    int i = r8 + 2 * half;
    size_t src = (size_t)blk * 1024 + e;
    size_t dst = (size_t)blk * 1024 + (((mt * 4 + k8) * 32 + lane) * 4 + i);
    g_Tf [dst] = to_tf32(g_T  [src]);
    g_M1f[dst] = to_tf32(g_M1 [src]);
    g_M2f[dst] = to_tf32(g_M2 [src]);
    g_Grf[dst] = to_tf32(g_Gre[src]);
    g_Gif[dst] = to_tf32(g_Gim[src]);
}

// ---------------- 0d. pre-permute W into tf32 MMA-fragment order ----------------
__global__ void wfrag_kernel(const float* __restrict__ out_w) {
    int idx = blockIdx.x * blockDim.x + threadIdx.x;    // NL*512*256
    if (idx >= NLn * 512 * 256) return;
    int layer = idx / (512 * 256);
    int rem = idx % (512 * 256);
    int m = rem / 256;
    int k = rem % 256;
    uint32_t val = to_tf32(out_w[idx]);

    int kc = k >> 4;
    int kk = (k >> 3) & 1;
    int tig = k & 3;
    int half = (k >> 2) & 1;
    int mt = m >> 4;
    int g = m & 7;
    int r8 = (m >> 3) & 1;
    int lane = 4 * g + tig;
    int i4 = r8 + 2 * half;
    int dst = (((kc * 32 + mt) * 2 + kk) * 32 + lane) * 4 + i4;
    g_wfrag[layer * 131072 + dst] = val;
}

// ---------------- 2. Toeplitz-chunk SSM scan on tensor cores ----------------
// Block: one h, 4 warps = 4 b's. grid = 256h x 8 b-groups = 2048 blocks, 128 thr.
__global__ __launch_bounds__(128) void scan_tc_kernel(const float* __restrict__ x,
                                                      const float* __restrict__ enc_w,
                                                      const float* __restrict__ enc_b,
                                                      int layer) {
    __shared__ uint32_t Tf [1024];       // frag order: [(mt*4+k8)*32+lane][4]
    __shared__ uint32_t M1f[1024];
    __shared__ uint32_t M2f[1024];
    __shared__ uint32_t Grf[1024];
    __shared__ uint32_t Gif[1024];
    __shared__ uint32_t Us [4][32][9];   // u tile tf32 [s][c]
    __shared__ float    Sre[4][32][9];   // S output / reused as y tile
    __shared__ float    Sim[4][32][9];
    __shared__ uint32_t Pre[4][32][9];   // s_prev tf32 bits [n][c]
    __shared__ uint32_t Pim[4][32][9];

    int tid = threadIdx.x;
    int warp = tid >> 5, lane = tid & 31;
    int g = lane >> 2, tig = lane & 3;
    int h = blockIdx.x >> 3;
    int b = (blockIdx.x & 7) * 4 + warp;

    // load per-h frag matrices: straight uint4 copies (2 per thread per matrix)
    size_t fb = (size_t)(layer * Hn + h) * 1024;
    {
        const uint4* s0 = reinterpret_cast<const uint4*>(g_Tf  + fb);
        const uint4* s1 = reinterpret_cast<const uint4*>(g_M1f + fb);
        const uint4* s2 = reinterpret_cast<const uint4*>(g_M2f + fb);
        const uint4* s3 = reinterpret_cast<const uint4*>(g_Grf + fb);
        const uint4* s4 = reinterpret_cast<const uint4*>(g_Gif + fb);
#pragma unroll
        for (int e = 0; e < 2; ++e) {
            int i4 = tid + e * 128;
            reinterpret_cast<uint4*>(Tf )[i4] = s0[i4];
            reinterpret_cast<uint4*>(M1f)[i4] = s1[i4];
            reinterpret_cast<uint4*>(M2f)[i4] = s2[i4];
            reinterpret_cast<uint4*>(Grf)[i4] = s3[i4];
            reinterpret_cast<uint4*>(Gif)[i4] = s4[i4];
        }
    }
    __syncthreads();

    float w32re_ = g_w32re[(size_t)(layer * Hn + h) * 32 + lane];
    float w32im_ = g_w32im[(size_t)(layer * Hn + h) * 32 + lane];

    size_t rowoff = ((size_t)b * Hn + h) * Ln;
    float* hrow = g_h + rowoff;
    uint32_t* yrow = g_y + rowoff;
    const float* xrow = x + (size_t)b * Ln;
    bool l0fuse = (layer == 0);
    float ew = l0fuse ? enc_w[h] : 0.0f;
    float eb = l0fuse ? enc_b[h] : 0.0f;

    float sre = 0.0f, sim = 0.0f;

    for (int gr = 0; gr < 16; ++gr) {
        int base_l = gr * 256;
        // ---- fill u tile [s=lane][c=i] ----
        if (l0fuse) {
#pragma unroll
            for (int i = 0; i < 8; ++i) {
                float v = fmaf(xrow[base_l + i * 32 + lane], ew, eb);
                hrow[base_l + i * 32 + lane] = v;
                Us[warp][lane][i] = to_tf32(v);
            }
        } else {
#pragma unroll
            for (int i = 0; i < 8; ++i)
                Us[warp][lane][i] = to_tf32(hrow[base_l + i * 32 + lane]);
        }
        __syncwarp();

        // ---- B fragments from u tile ----
        uint2 bu[4];
#pragma unroll
        for (int k8 = 0; k8 < 4; ++k8) {
            bu[k8].x = Us[warp][k8 * 8 + tig][g];
            bu[k8].y = Us[warp][k8 * 8 + tig + 4][g];
        }

        // ---- S = Gre@U, Gim@U ----
        float fre[2][4], fim[2][4];
#pragma unroll
        for (int mt = 0; mt < 2; ++mt)
#pragma unroll
            for (int r = 0; r < 4; ++r) { fre[mt][r] = 0.0f; fim[mt][r] = 0.0f; }
#pragma unroll
        for (int mt = 0; mt < 2; ++mt) {
#pragma unroll
            for (int k8 = 0; k8 < 4; ++k8) {
                int fo = ((mt * 4 + k8) * 32 + lane) * 4;
                mma_tf32(fre[mt], *reinterpret_cast<const uint4*>(&Grf[fo]), bu[k8]);
                mma_tf32(fim[mt], *reinterpret_cast<const uint4*>(&Gif[fo]), bu[k8]);
            }
        }
#pragma unroll
        for (int mt = 0; mt < 2; ++mt) {
            int mr = mt * 16;
            Sre[warp][mr + g][2 * tig]     = fre[mt][0];
            Sre[warp][mr + g][2 * tig + 1] = fre[mt][1];
            Sre[warp][mr + g + 8][2 * tig]     = fre[mt][2];
            Sre[warp][mr + g + 8][2 * tig + 1] = fre[mt][3];
            Sim[warp][mr + g][2 * tig]     = fim[mt][0];
            Sim[warp][mr + g][2 * tig + 1] = fim[mt][1];
            Sim[warp][mr + g + 8][2 * tig]     = fim[mt][2];
            Sim[warp][mr + g + 8][2 * tig + 1] = fim[mt][3];
        }
        __syncwarp();

        // ---- sequential scan over 8 chunks (lane = state n) ----
#pragma unroll
        for (int c = 0; c < 8; ++c) {
            Pre[warp][lane][c] = to_tf32(sre);
            Pim[warp][lane][c] = to_tf32(sim);
            float S_re = Sre[warp][lane][c];
            float S_im = Sim[warp][lane][c];
            float nre = fmaf(w32re_, sre, fmaf(-w32im_, sim, S_re));
            float nim = fmaf(w32re_, sim, fmaf(w32im_, sre, S_im));
            sre = nre; sim = nim;
        }
        __syncwarp();

        // ---- Y = T@U + M1@Sprev_re + M2@Sprev_im ----
        float yf[2][4];
#pragma unroll
        for (int mt = 0; mt < 2; ++mt)
#pragma unroll
            for (int r = 0; r < 4; ++r) yf[mt][r] = 0.0f;
        uint2 bp[4], bq[4];
#pragma unroll
        for (int k8 = 0; k8 < 4; ++k8) {
            bp[k8].x = Pre[warp][k8 * 8 + tig][g];
            bp[k8].y = Pre[warp][k8 * 8 + tig + 4][g];
            bq[k8].x = Pim[warp][k8 * 8 + tig][g];
            bq[k8].y = Pim[warp][k8 * 8 + tig + 4][g];
        }
#pragma unroll
        for (int mt = 0; mt < 2; ++mt) {
#pragma unroll
            for (int k8 = 0; k8 < 4; ++k8) {
                int fo = ((mt * 4 + k8) * 32 + lane) * 4;
                mma_tf32(yf[mt], *reinterpret_cast<const uint4*>(&Tf [fo]), bu[k8]);
                mma_tf32(yf[mt], *reinterpret_cast<const uint4*>(&M1f[fo]), bp[k8]);
                mma_tf32(yf[mt], *reinterpret_cast<const uint4*>(&M2f[fo]), bq[k8]);
            }
        }
        // ---- stage Y to smem (reuse Sre), then gelu + store ----
#pragma unroll
        for (int mt = 0; mt < 2; ++mt) {
            int mr = mt * 16;
            Sre[warp][mr + g][2 * tig]     = yf[mt][0];
            Sre[warp][mr + g][2 * tig + 1] = yf[mt][1];
            Sre[warp][mr + g + 8][2 * tig]     = yf[mt][2];
            Sre[warp][mr + g + 8][2 * tig + 1] = yf[mt][3];
        }
        __syncwarp();
#pragma unroll
        for (int i = 0; i < 8; ++i) {
            float v = Sre[warp][lane][i];      // y[t=lane][c=i]
            yrow[base_l + i * 32 + lane] = to_tf32(gelu_tanh(v));
        }
        __syncwarp();
    }
}

// ---------------- 3. tf32 tensor-core GEMM, fragment-ordered A ----------------
__global__ __launch_bounds__(256) void gemm_tc_kernel(const float* __restrict__ out_b,
                                                      int layer) {
    __shared__ uint32_t As[8192];
    __shared__ uint32_t Bs[16][132];

    int b = blockIdx.z;
    const uint32_t* Yb = g_y + (size_t)b * Hn * Ln;
    float* Z = g_z + (size_t)b * 2 * Hn * Ln;
    const uint32_t* Wf = g_wfrag + layer * 131072;
    const float* obl = out_b + layer * 2 * Hn;

    int n0 = blockIdx.x * 128;
    int m0 = blockIdx.y * 128;
    int mt0 = m0 >> 4;

    int tid = threadIdx.x;
    int warp = tid >> 5, lane = tid & 31;
    int wm = warp >> 2;
    int wn = warp & 3;
    int g = lane >> 2, tig = lane & 3;

    float acc[4][4][4];
#pragma unroll
    for (int mt = 0; mt < 4; ++mt)
#pragma unroll
        for (int nt = 0; nt < 4; ++nt)
#pragma unroll
            for (int r = 0; r < 4; ++r) acc[mt][nt][r] = 0.0f;

    uint4 pa[2], pb[2];
    {
        const uint4* srcA = reinterpret_cast<const uint4*>(Wf + (0 * 32 + mt0) * 256);
        pa[0] = srcA[tid];
        pa[1] = srcA[tid + 256];
#pragma unroll
        for (int j = 0; j < 2; ++j) {
            int idx4 = tid + j * 256;
            int r = idx4 >> 5, c4 = idx4 & 31;
            pb[j] = *reinterpret_cast<const uint4*>(&Yb[(size_t)r * Ln + n0 + c4 * 4]);
        }
    }

    for (int kc = 0; kc < 16; ++kc) {
        reinterpret_cast<uint4*>(As)[tid] = pa[0];
        reinterpret_cast<uint4*>(As)[tid + 256] = pa[1];
#pragma unroll
        for (int j = 0; j < 2; ++j) {
            int idx4 = tid + j * 256;
            int r = idx4 >> 5, c4 = idx4 & 31;
            *reinterpret_cast<uint4*>(&Bs[r][c4 * 4]) = pb[j];
        }
        __syncthreads();

        if (kc + 1 < 16) {
            const uint4* srcA = reinterpret_cast<const uint4*>(Wf + ((kc + 1) * 32 + mt0) * 256);
            pa[0] = srcA[tid];
            pa[1] = srcA[tid + 256];
#pragma unroll
            for (int j = 0; j < 2; ++j) {
                int idx4 = tid + j * 256;
                int r = idx4 >> 5, c4 = idx4 & 31;
                pb[j] = *reinterpret_cast<const uint4*>(
                    &Yb[(size_t)((kc + 1) * 16 + r) * Ln + n0 + c4 * 4]);
            }
        }

#pragma unroll
        for (int kk = 0; kk < 2; ++kk) {
            int k8 = kk * 8;
            uint4 afr[4];
#pragma unroll
            for (int mt = 0; mt < 4; ++mt)
                afr[mt] = *reinterpret_cast<const uint4*>(
                    &As[(((wm * 4 + mt) * 2 + kk) * 32 + lane) * 4]);
            uint2 bfr[4];
#pragma unroll
            for (int nt = 0; nt < 4; ++nt) {
                int ncol = wn * 32 + nt * 8;
                bfr[nt].x = Bs[k8 + tig][ncol + g];
                bfr[nt].y = Bs[k8 + tig + 4][ncol + g];
            }
#pragma unroll
            for (int mt = 0; mt < 4; ++mt)
#pragma unroll
                for (int nt = 0; nt < 4; ++nt)
                    mma_tf32(acc[mt][nt], afr[mt], bfr[nt]);
        }
        __syncthreads();
    }

#pragma unroll
    for (int mt = 0; mt < 4; ++mt) {
        int m = m0 + wm * 64 + mt * 16 + g;
        float bias0 = obl[m];
        float bias1 = obl[m + 8];
#pragma unroll
        for (int nt = 0; nt < 4; ++nt) {
            int n = n0 + wn * 32 + nt * 8 + 2 * tig;
            float2 v0 = make_float2(acc[mt][nt][0] + bias0, acc[mt][nt][1] + bias0);
            float2 v1 = make_float2(acc[mt][nt][2] + bias1, acc[mt][nt][3] + bias1);
            *reinterpret_cast<float2*>(&Z[(size_t)m * Ln + n]) = v0;
            *reinterpret_cast<float2*>(&Z[(size_t)(m + 8) * Ln + n]) = v1;
        }
    }
}

// ---------------- 4. GLU + residual + LayerNorm (in-place on g_h) ----------------
__global__ __launch_bounds__(256) void glu_ln_kernel(const float* __restrict__ ln_w_all,
                                                     const float* __restrict__ ln_b_all,
                                                     int layer) {
    int b = blockIdx.y;
    int l0 = blockIdx.x * 32;
    const float* Z = g_z + (size_t)b * 2 * Hn * Ln;
    float* Hb = g_h + (size_t)b * Hn * Ln;
    const float* lnw = ln_w_all + layer * Hn;
    const float* lnb = ln_b_all + layer * Hn;

    __shared__ float t[Hn][33];
    __shared__ float mu_s[32], rs_s[32];

    int tx = threadIdx.x & 31;
    int ty = threadIdx.x >> 5;

    for (int oo = 0; oo < Hn; oo += 8) {
        int o = oo + ty;
        float a = Z[(size_t)o * Ln + l0 + tx];
        float g = Z[(size_t)(o + Hn) * Ln + l0 + tx];
        float hold = Hb[(size_t)o * Ln + l0 + tx];
        t[o][tx] = a * sigmoidf_(g) + hold;
    }
    __syncthreads();

    for (int c = ty; c < 32; c += 8) {
        float s = 0.0f, s2 = 0.0f;
#pragma unroll
        for (int k = 0; k < 8; ++k) {
            float v = t[tx + 32 * k][c];
            s += v; s2 += v * v;
        }
#pragma unroll
        for (int off = 16; off > 0; off >>= 1) {
            s += __shfl_xor_sync(0xffffffffu, s, off);
            s2 += __shfl_xor_sync(0xffffffffu, s2, off);
        }
        if (tx == 0) {
            float mu = s * (1.0f / Hn);
            float var = s2 * (1.0f / Hn) - mu * mu;
            mu_s[c] = mu;
            rs_s[c] = rsqrtf(var + 1e-5f);
        }
    }
    __syncthreads();

    for (int oo = 0; oo < Hn; oo += 8) {
        int o = oo + ty;
        float v = (t[o][tx] - mu_s[tx]) * rs_s[tx] * lnw[o] + lnb[o];
        Hb[(size_t)o * Ln + l0 + tx] = v;
    }
}

// ---------------- 5. mean pool over L ----------------
__global__ void pool_kernel() {
    int row = blockIdx.x;  // b*H+h
    const float* p = g_h + (size_t)row * Ln;
    float s = 0.0f;
    for (int l = threadIdx.x; l < Ln; l += 256) s += p[l];
    __shared__ float red[256];
    red[threadIdx.x] = s;
    __syncthreads();
    for (int off = 128; off > 0; off >>= 1) {
        if (threadIdx.x < off) red[threadIdx.x] += red[threadIdx.x + off];
        __syncthreads();
    }
    if (threadIdx.x == 0) g_pool[row] = red[0] * (1.0f / Ln);
}

// ---------------- 6. decoder ----------------
__global__ void decode_kernel(const float* __restrict__ dec_w,
                              const float* __restrict__ dec_b,
                              float* __restrict__ out) {
    int idx = threadIdx.x;      // 256 = B*DOUT
    int b = idx >> 3, d = idx & 7;
    float s = dec_b[d];
    for (int h = 0; h < Hn; ++h)
        s += g_pool[b * Hn + h] * dec_w[d * Hn + h];
    out[idx] = sigmoidf_(s);
}

// ---------------- launch ----------------
extern "C" void kernel_launch(void* const* d_in, const int* in_sizes, int n_in,
                              void* d_out, int out_size) {
    const float* x          = (const float*)d_in[0];
    const float* enc_w      = (const float*)d_in[1];
    const float* enc_b      = (const float*)d_in[2];
    const float* log_dt     = (const float*)d_in[3];
    const float* C_re       = (const float*)d_in[4];
    const float* C_im       = (const float*)d_in[5];
    const float* log_A_real = (const float*)d_in[6];
    const float* A_imag     = (const float*)d_in[7];
    const float* D          = (const float*)d_in[8];
    const float* out_w      = (const float*)d_in[9];
    const float* out_b      = (const float*)d_in[10];
    const float* ln_w       = (const float*)d_in[11];
    const float* ln_b       = (const float*)d_in[12];
    const float* dec_w      = (const float*)d_in[13];
    const float* dec_b      = (const float*)d_in[14];
    float* out = (float*)d_out;

    precompute_kernel<<<(NLn * Hn * N2n + 255) / 256, 256>>>(log_dt, C_re, C_im,
                                                             log_A_real, A_imag);
    precompute2_kernel<<<(NLn * Hn) / 8, 256>>>(D);
    fragmat_kernel<<<(NLn * Hn * 1024 + 255) / 256, 256>>>();
    wfrag_kernel<<<(NLn * 512 * 256 + 255) / 256, 256>>>(out_w);

    dim3 ggrid(Ln / 128, 512 / 128, Bn);
    dim3 egrid(Ln / 32, Bn);

    for (int i = 0; i < NLn; ++i) {
        scan_tc_kernel<<<Hn * 8, 128>>>(x, enc_w, enc_b, i);
        gemm_tc_kernel<<<ggrid, 256>>>(out_b, i);
        glu_ln_kernel<<<egrid, 256>>>(ln_w, ln_b, i);
    }

    pool_kernel<<<Bn * Hn, 256>>>();
    decode_kernel<<<1, 256>>>(dec_w, dec_b, out);
}

// round 14
// speedup vs baseline: 1.4278x; 1.0358x over previous
#include <cuda_runtime.h>
#include <cuda_bf16.h>
#include <math.h>
#include <stdint.h>

// Problem constants
#define Bn   32
#define Ln   4096
#define Hn   256
#define N2n  32
#define NLn  4
#define DOUTn 8

// ---------------- scratch (device globals; no allocation allowed) ----------------
__device__ float    g_h[(size_t)Bn * Hn * Ln];     // 128 MB  current hidden (B,H,L)
__device__ uint32_t g_y[(size_t)Bn * Hn * Ln];     // 128 MB  tf32 bits of gelu(ssm) (B,H,L)
__device__ float    g_z[(size_t)Bn * 2 * Hn * Ln]; // 256 MB  GEMM output (B,2H,L)
__device__ float    g_par[NLn * 4 * Hn * N2n];     // w_re,w_im,cd_re,cd_im (2x folded)
__device__ uint32_t g_wfrag[NLn * 512 * 256];      // W as tf32 bits, MMA-fragment order
__device__ float    g_pool[Bn * Hn];
__device__ float    g_poolpart[Bn * Hn * (Ln / 32)];  // 4 MB partial pool sums
// Toeplitz-scan matrices, per (layer,h): 32x32 each, row-major (fp32 staging)
__device__ float    g_T  [NLn * Hn * 1024];
__device__ float    g_M1 [NLn * Hn * 1024];
__device__ float    g_M2 [NLn * Hn * 1024];
__device__ float    g_Gre[NLn * Hn * 1024];
__device__ float    g_Gim[NLn * Hn * 1024];
// fragment-ordered tf32 versions: [mt(2)][k8(4)][lane(32)][4]
__device__ uint32_t g_Tf  [NLn * Hn * 1024];
__device__ uint32_t g_M1f [NLn * Hn * 1024];
__device__ uint32_t g_M2f [NLn * Hn * 1024];
__device__ uint32_t g_Grf [NLn * Hn * 1024];
__device__ uint32_t g_Gif [NLn * Hn * 1024];
__device__ float    g_w32re[NLn * Hn * 32];
__device__ float    g_w32im[NLn * Hn * 32];

// ---------------- helpers ----------------
__device__ __forceinline__ float gelu_tanh(float x) {
    float x3 = x * x * x;
    float t = tanhf(0.7978845608028654f * (x + 0.044715f * x3));
    return 0.5f * x * (1.0f + t);
}
__device__ __forceinline__ float sigmoidf_(float x) {
    return 1.0f / (1.0f + expf(-x));
}
__device__ __forceinline__ uint32_t to_tf32(float x) {
    uint32_t r;
    asm("cvt.rna.tf32.f32 %0, %1;" : "=r"(r) : "f"(x));
    return r;
}
__device__ __forceinline__ void cp_async16(void* smem_dst, const void* gsrc) {
    uint32_t s = (uint32_t)__cvta_generic_to_shared(smem_dst);
    asm volatile("cp.async.cg.shared.global [%0], [%1], 16;\n" :: "r"(s), "l"(gsrc));
}
#define CP_COMMIT() asm volatile("cp.async.commit_group;\n" ::: "memory")
#define CP_WAIT1()  asm volatile("cp.async.wait_group 1;\n" ::: "memory")
#define CP_WAIT0()  asm volatile("cp.async.wait_group 0;\n" ::: "memory")

// mma.sync m16n8k8 tf32: D = A@B + D   (A,B as raw b32 tf32 bit patterns)
__device__ __forceinline__ void mma_tf32(float (&d)[4], const uint4& a, const uint2& b) {
    asm volatile(
        "mma.sync.aligned.m16n8k8.row.col.f32.tf32.tf32.f32 "
        "{%0,%1,%2,%3}, {%4,%5,%6,%7}, {%8,%9}, {%0,%1,%2,%3};\n"
        : "+f"(d[0]), "+f"(d[1]), "+f"(d[2]), "+f"(d[3])
        : "r"(a.x), "r"(a.y), "r"(a.z), "r"(a.w), "r"(b.x), "r"(b.y));
}

// ---------------- 0a. precompute discretized SSM params ----------------
__global__ void precompute_kernel(const float* __restrict__ log_dt,
                                  const float* __restrict__ C_re,
                                  const float* __restrict__ C_im,
                                  const float* __restrict__ log_A_real,
                                  const float* __restrict__ A_imag) {
    int idx = blockIdx.x * blockDim.x + threadIdx.x;      // NL*H*N2
    if (idx >= NLn * Hn * N2n) return;
    int i = idx / (Hn * N2n);
    int rem = idx % (Hn * N2n);
    int h = rem / N2n;

    float dt = expf(log_dt[i * Hn + h]);
    float Are = -expf(log_A_real[idx]);
    float Aim = A_imag[idx];
    float dre = Are * dt, dim = Aim * dt;
    float e = expf(dre);
    float w_re = e * cosf(dim);
    float w_im = e * sinf(dim);
    float inv = 1.0f / (Are * Are + Aim * Aim);
    float nre = w_re - 1.0f, nim = w_im;
    float fre = (nre * Are + nim * Aim) * inv;
    float fim = (nim * Are - nre * Aim) * inv;
    float cre = C_re[idx], cim = C_im[idx];
    float cd_re = cre * fre - cim * fim;
    float cd_im = cre * fim + cim * fre;

    int base = ((i * 4 + 0) * Hn + h) * N2n + (idx % N2n);
    int stride = Hn * N2n;
    g_par[base + 0 * stride] = w_re;
    g_par[base + 1 * stride] = w_im;
    g_par[base + 2 * stride] = 2.0f * cd_re;   // fold the 2x into C
    g_par[base + 3 * stride] = 2.0f * cd_im;
}

// ---------------- 0b. build Toeplitz-scan matrices per (layer,h) ----------------
__global__ __launch_bounds__(256) void precompute2_kernel(const float* __restrict__ Dmat) {
    __shared__ float kbuf[8][33];
    int warp = threadIdx.x >> 5, lane = threadIdx.x & 31;
    int idx = blockIdx.x * 8 + warp;           // 0..NL*Hn-1
    if (idx >= NLn * Hn) return;
    int l = idx >> 8, h = idx & 255;

    int pstride = Hn * N2n;
    int pbase = ((l * 4) * Hn + h) * N2n + lane;
    float wre = g_par[pbase + 0 * pstride];
    float wim = g_par[pbase + 1 * pstride];
    float cre = g_par[pbase + 2 * pstride];    // 2*Cd
    float cim = g_par[pbase + 3 * pstride];
    float Dh = Dmat[l * Hn + h];

    size_t mbase = (size_t)idx * 1024;

    float pre = 1.0f, pim = 0.0f;              // w^0
    for (int d = 0; d <= 32; ++d) {
        float m1 = cre * pre - cim * pim;        // Re(Cd w^d)
        float m2 = -(cre * pim + cim * pre);     // -Im(Cd w^d)
        if (d >= 1) {
            g_M1[mbase + (size_t)(d - 1) * 32 + lane] = m1;   // M1[t=d-1][n]
            g_M2[mbase + (size_t)(d - 1) * 32 + lane] = m2;
        }
        if (d < 32) {
            float kd = m1;
#pragma unroll
            for (int off = 16; off > 0; off >>= 1)
                kd += __shfl_xor_sync(0xffffffffu, kd, off);
            if (lane == 0) kbuf[warp][d] = kd;
            g_Gre[mbase + (size_t)lane * 32 + (31 - d)] = pre;
            g_Gim[mbase + (size_t)lane * 32 + (31 - d)] = pim;
        }
        if (d == 32) {
            g_w32re[(size_t)idx * 32 + lane] = pre;
            g_w32im[(size_t)idx * 32 + lane] = pim;
        }
        float npre = pre * wre - pim * wim;
        float npim = pre * wim + pim * wre;
        pre = npre; pim = npim;
    }
    __syncwarp();
    for (int e = lane; e < 1024; e += 32) {
        int t = e >> 5, s = e & 31;
        float v = 0.0f;
        if (t > s) v = kbuf[warp][t - s];
        else if (t == s) v = kbuf[warp][0] + Dh;
        g_T[mbase + e] = v;
    }
}

// ---------------- 0c. fragment-order the scan matrices (tf32 bits) ----------------
__global__ void fragmat_kernel() {
    int idx = blockIdx.x * blockDim.x + threadIdx.x;   // NL*Hn*1024
    if (idx >= NLn * Hn * 1024) return;
    int blk = idx >> 10;           // (layer,h)
    int e = idx & 1023;
    int t = e >> 5, s = e & 31;
    int mt = t >> 4;
    int g = t & 7;
    int r8 = (t >> 3) & 1;
    int k8 = s >> 3;
    int tig = s & 3;
    int half = (s >> 2) & 1;
    int lane = 4 * g + tig;
    int i = r8 + 2 * half;
    size_t src = (size_t)blk * 1024 + e;
    size_t dst = (size_t)blk * 1024 + (((mt * 4 + k8) * 32 + lane) * 4 + i);
    g_Tf [dst] = to_tf32(g_T  [src]);
    g_M1f[dst] = to_tf32(g_M1 [src]);
    g_M2f[dst] = to_tf32(g_M2 [src]);
    g_Grf[dst] = to_tf32(g_Gre[src]);
    g_Gif[dst] = to_tf32(g_Gim[src]);
}

// ---------------- 0d. pre-permute W into tf32 MMA-fragment order ----------------
__global__ void wfrag_kernel(const float* __restrict__ out_w) {
    int idx = blockIdx.x * blockDim.x + threadIdx.x;    // NL*512*256
    if (idx >= NLn * 512 * 256) return;
    int layer = idx / (512 * 256);
    int rem = idx % (512 * 256);
    int m = rem / 256;
    int k = rem % 256;
    uint32_t val = to_tf32(out_w[idx]);

    int kc = k >> 4;
    int kk = (k >> 3) & 1;
    int tig = k & 3;
    int half = (k >> 2) & 1;
    int mt = m >> 4;
    int g = m & 7;
    int r8 = (m >> 3) & 1;
    int lane = 4 * g + tig;
    int i4 = r8 + 2 * half;
    int dst = (((kc * 32 + mt) * 2 + kk) * 32 + lane) * 4 + i4;
    g_wfrag[layer * 131072 + dst] = val;
}

// ---------------- 2. Toeplitz-chunk SSM scan on tensor cores ----------------
// Block: one h, 4 warps = 4 b's. grid = 256h x 8 b-groups = 2048 blocks, 128 thr.
__global__ __launch_bounds__(128) void scan_tc_kernel(const float* __restrict__ x,
                                                      const float* __restrict__ enc_w,
                                                      const float* __restrict__ enc_b,
                                                      int layer) {
    __shared__ uint32_t Tf [1024];       // frag order: [(mt*4+k8)*32+lane][4]
    __shared__ uint32_t M1f[1024];
    __shared__ uint32_t M2f[1024];
    __shared__ uint32_t Grf[1024];
    __shared__ uint32_t Gif[1024];
    __shared__ uint32_t Us [4][32][9];   // u tile tf32 [s][c]
    __shared__ float    Sre[4][32][9];   // S output / reused as y tile
    __shared__ float    Sim[4][32][9];
    __shared__ uint32_t Pre[4][32][9];   // s_prev tf32 bits [n][c]
    __shared__ uint32_t Pim[4][32][9];

    int tid = threadIdx.x;
    int warp = tid >> 5, lane = tid & 31;
    int g = lane >> 2, tig = lane & 3;
    int h = blockIdx.x >> 3;
    int b = (blockIdx.x & 7) * 4 + warp;

    // load per-h frag matrices: straight uint4 copies (2 per thread per matrix)
    size_t fb = (size_t)(layer * Hn + h) * 1024;
    {
        const uint4* s0 = reinterpret_cast<const uint4*>(g_Tf  + fb);
        const uint4* s1 = reinterpret_cast<const uint4*>(g_M1f + fb);
        const uint4* s2 = reinterpret_cast<const uint4*>(g_M2f + fb);
        const uint4* s3 = reinterpret_cast<const uint4*>(g_Grf + fb);
        const uint4* s4 = reinterpret_cast<const uint4*>(g_Gif + fb);
#pragma unroll
        for (int e = 0; e < 2; ++e) {
            int i4 = tid + e * 128;
            reinterpret_cast<uint4*>(Tf )[i4] = s0[i4];
            reinterpret_cast<uint4*>(M1f)[i4] = s1[i4];
            reinterpret_cast<uint4*>(M2f)[i4] = s2[i4];
            reinterpret_cast<uint4*>(Grf)[i4] = s3[i4];
            reinterpret_cast<uint4*>(Gif)[i4] = s4[i4];
        }
    }
    __syncthreads();

    float w32re_ = g_w32re[(size_t)(layer * Hn + h) * 32 + lane];
    float w32im_ = g_w32im[(size_t)(layer * Hn + h) * 32 + lane];

    size_t rowoff = ((size_t)b * Hn + h) * Ln;
    float* hrow = g_h + rowoff;
    uint32_t* yrow = g_y + rowoff;
    const float* xrow = x + (size_t)b * Ln;
    bool l0fuse = (layer == 0);
    float ew = l0fuse ? enc_w[h] : 0.0f;
    float eb = l0fuse ? enc_b[h] : 0.0f;

    float sre = 0.0f, sim = 0.0f;

    for (int gr = 0; gr < 16; ++gr) {
        int base_l = gr * 256;
        // ---- fill u tile [s=lane][c=i] ----
        if (l0fuse) {
#pragma unroll
            for (int i = 0; i < 8; ++i) {
                float v = fmaf(xrow[base_l + i * 32 + lane], ew, eb);
                hrow[base_l + i * 32 + lane] = v;
                Us[warp][lane][i] = to_tf32(v);
            }
        } else {
#pragma unroll
            for (int i = 0; i < 8; ++i)
                Us[warp][lane][i] = to_tf32(hrow[base_l + i * 32 + lane]);
        }
        __syncwarp();

        // ---- B fragments from u tile ----
        uint2 bu[4];
#pragma unroll
        for (int k8 = 0; k8 < 4; ++k8) {
            bu[k8].x = Us[warp][k8 * 8 + tig][g];
            bu[k8].y = Us[warp][k8 * 8 + tig + 4][g];
        }

        // ---- S = Gre@U, Gim@U ----
        float fre[2][4], fim[2][4];
#pragma unroll
        for (int mt = 0; mt < 2; ++mt)
#pragma unroll
            for (int r = 0; r < 4; ++r) { fre[mt][r] = 0.0f; fim[mt][r] = 0.0f; }
#pragma unroll
        for (int mt = 0; mt < 2; ++mt) {
#pragma unroll
            for (int k8 = 0; k8 < 4; ++k8) {
                int fo = ((mt * 4 + k8) * 32 + lane) * 4;
                mma_tf32(fre[mt], *reinterpret_cast<const uint4*>(&Grf[fo]), bu[k8]);
                mma_tf32(fim[mt], *reinterpret_cast<const uint4*>(&Gif[fo]), bu[k8]);
            }
        }
#pragma unroll
        for (int mt = 0; mt < 2; ++mt) {
            int mr = mt * 16;
            Sre[warp][mr + g][2 * tig]     = fre[mt][0];
            Sre[warp][mr + g][2 * tig + 1] = fre[mt][1];
            Sre[warp][mr + g + 8][2 * tig]     = fre[mt][2];
            Sre[warp][mr + g + 8][2 * tig + 1] = fre[mt][3];
            Sim[warp][mr + g][2 * tig]     = fim[mt][0];
            Sim[warp][mr + g][2 * tig + 1] = fim[mt][1];
            Sim[warp][mr + g + 8][2 * tig]     = fim[mt][2];
            Sim[warp][mr + g + 8][2 * tig + 1] = fim[mt][3];
        }
        __syncwarp();

        // ---- sequential scan over 8 chunks (lane = state n) ----
#pragma unroll
        for (int c = 0; c < 8; ++c) {
            Pre[warp][lane][c] = to_tf32(sre);
            Pim[warp][lane][c] = to_tf32(sim);
            float S_re = Sre[warp][lane][c];
            float S_im = Sim[warp][lane][c];
            float nre = fmaf(w32re_, sre, fmaf(-w32im_, sim, S_re));
            float nim = fmaf(w32re_, sim, fmaf(w32im_, sre, S_im));
            sre = nre; sim = nim;
        }
        __syncwarp();

        // ---- Y = T@U + M1@Sprev_re + M2@Sprev_im ----
        float yf[2][4];
#pragma unroll
        for (int mt = 0; mt < 2; ++mt)
#pragma unroll
            for (int r = 0; r < 4; ++r) yf[mt][r] = 0.0f;
        uint2 bp[4], bq[4];
#pragma unroll
        for (int k8 = 0; k8 < 4; ++k8) {
            bp[k8].x = Pre[warp][k8 * 8 + tig][g];
            bp[k8].y = Pre[warp][k8 * 8 + tig + 4][g];
            bq[k8].x = Pim[warp][k8 * 8 + tig][g];
            bq[k8].y = Pim[warp][k8 * 8 + tig + 4][g];
        }
#pragma unroll
        for (int mt = 0; mt < 2; ++mt) {
#pragma unroll
            for (int k8 = 0; k8 < 4; ++k8) {
                int fo = ((mt * 4 + k8) * 32 + lane) * 4;
                mma_tf32(yf[mt], *reinterpret_cast<const uint4*>(&Tf [fo]), bu[k8]);
                mma_tf32(yf[mt], *reinterpret_cast<const uint4*>(&M1f[fo]), bp[k8]);
                mma_tf32(yf[mt], *reinterpret_cast<const uint4*>(&M2f[fo]), bq[k8]);
            }
        }
        // ---- stage Y to smem (reuse Sre), then gelu + store ----
#pragma unroll
        for (int mt = 0; mt < 2; ++mt) {
            int mr = mt * 16;
            Sre[warp][mr + g][2 * tig]     = yf[mt][0];
            Sre[warp][mr + g][2 * tig + 1] = yf[mt][1];
            Sre[warp][mr + g + 8][2 * tig]     = yf[mt][2];
            Sre[warp][mr + g + 8][2 * tig + 1] = yf[mt][3];
        }
        __syncwarp();
#pragma unroll
        for (int i = 0; i < 8; ++i) {
            float v = Sre[warp][lane][i];      // y[t=lane][c=i]
            yrow[base_l + i * 32 + lane] = to_tf32(gelu_tanh(v));
        }
        __syncwarp();
    }
}

// ---------------- 3. tf32 GEMM: cp.async 2-stage pipeline, fragment-ordered A ----
__global__ __launch_bounds__(256) void gemm_tc_kernel(const float* __restrict__ out_b,
                                                      int layer) {
    __shared__ uint32_t As[2][2048];      // per-kc A chunk (frag order), 2 stages
    __shared__ uint32_t Bs[2][16][132];   // per-kc B chunk [k][n] pad 132, 2 stages

    int b = blockIdx.z;
    const uint32_t* Yb = g_y + (size_t)b * Hn * Ln;
    float* Z = g_z + (size_t)b * 2 * Hn * Ln;
    const uint32_t* Wf = g_wfrag + layer * 131072;
    const float* obl = out_b + layer * 2 * Hn;

    int n0 = blockIdx.x * 128;
    int m0 = blockIdx.y * 128;
    int mt0 = m0 >> 4;

    int tid = threadIdx.x;
    int warp = tid >> 5, lane = tid & 31;
    int wm = warp >> 2;
    int wn = warp & 3;
    int g = lane >> 2, tig = lane & 3;

    // B copy indices (fixed per thread)
    int br0 = tid >> 5, bc0 = (tid & 31) * 4;          // j=0
    int br1 = (tid + 256) >> 5, bc1 = bc0;             // j=1 (row +8)

    float acc[4][4][4];
#pragma unroll
    for (int mt = 0; mt < 4; ++mt)
#pragma unroll
        for (int nt = 0; nt < 4; ++nt)
#pragma unroll
            for (int r = 0; r < 4; ++r) acc[mt][nt][r] = 0.0f;

    // async tile loader: A 2 x 16B/thread, B 2 x 16B/thread
    auto load_tile = [&](int kc, int s) {
        const uint4* srcA = reinterpret_cast<const uint4*>(Wf + (kc * 32 + mt0) * 256);
        cp_async16(&reinterpret_cast<uint4*>(As[s])[tid], srcA + tid);
        cp_async16(&reinterpret_cast<uint4*>(As[s])[tid + 256], srcA + tid + 256);
        cp_async16(&Bs[s][br0][bc0], &Yb[(size_t)(kc * 16 + br0) * Ln + n0 + bc0]);
        cp_async16(&Bs[s][br1][bc1], &Yb[(size_t)(kc * 16 + br1) * Ln + n0 + bc1]);
    };

    load_tile(0, 0); CP_COMMIT();
    load_tile(1, 1); CP_COMMIT();

    for (int kc = 0; kc < 16; ++kc) {
        if (kc < 14) CP_WAIT1(); else CP_WAIT0();
        __syncthreads();
        int s = kc & 1;

#pragma unroll
        for (int kk = 0; kk < 2; ++kk) {
            int k8 = kk * 8;
            uint4 afr[4];
#pragma unroll
            for (int mt = 0; mt < 4; ++mt)
                afr[mt] = *reinterpret_cast<const uint4*>(
                    &As[s][(((wm * 4 + mt) * 2 + kk) * 32 + lane) * 4]);
            uint2 bfr[4];
#pragma unroll
            for (int nt = 0; nt < 4; ++nt) {
                int ncol = wn * 32 + nt * 8;
                bfr[nt].x = Bs[s][k8 + tig][ncol + g];
                bfr[nt].y = Bs[s][k8 + tig + 4][ncol + g];
            }
#pragma unroll
            for (int mt = 0; mt < 4; ++mt)
#pragma unroll
                for (int nt = 0; nt < 4; ++nt)
                    mma_tf32(acc[mt][nt], afr[mt], bfr[nt]);
        }
        __syncthreads();
        if (kc + 2 < 16) { load_tile(kc + 2, s); CP_COMMIT(); }
    }

#pragma unroll
    for (int mt = 0; mt < 4; ++mt) {
        int m = m0 + wm * 64 + mt * 16 + g;
        float bias0 = obl[m];
        float bias1 = obl[m + 8];
#pragma unroll
        for (int nt = 0; nt < 4; ++nt) {
            int n = n0 + wn * 32 + nt * 8 + 2 * tig;
            float2 v0 = make_float2(acc[mt][nt][0] + bias0, acc[mt][nt][1] + bias0);
            float2 v1 = make_float2(acc[mt][nt][2] + bias1, acc[mt][nt][3] + bias1);
            *reinterpret_cast<float2*>(&Z[(size_t)m * Ln + n]) = v0;
            *reinterpret_cast<float2*>(&Z[(size_t)(m + 8) * Ln + n]) = v1;
        }
    }
}

// ---------------- 4. GLU + residual + LayerNorm (last layer: emit pool partials) --
__global__ __launch_bounds__(256) void glu_ln_kernel(const float* __restrict__ ln_w_all,
                                                     const float* __restrict__ ln_b_all,
                                                     int layer, int last) {
    int b = blockIdx.y;
    int l0 = blockIdx.x * 32;
    const float* Z = g_z + (size_t)b * 2 * Hn * Ln;
    float* Hb = g_h + (size_t)b * Hn * Ln;
    const float* lnw = ln_w_all + layer * Hn;
    const float* lnb = ln_b_all + layer * Hn;

    __shared__ float t[Hn][33];
    __shared__ float mu_s[32], rs_s[32];

    int tx = threadIdx.x & 31;
    int ty = threadIdx.x >> 5;

    for (int oo = 0; oo < Hn; oo += 8) {
        int o = oo + ty;
        float a = Z[(size_t)o * Ln + l0 + tx];
        float g = Z[(size_t)(o + Hn) * Ln + l0 + tx];
        float hold = Hb[(size_t)o * Ln + l0 + tx];
        t[o][tx] = a * sigmoidf_(g) + hold;
    }
    __syncthreads();

    for (int c = ty; c < 32; c += 8) {
        float s = 0.0f, s2 = 0.0f;
#pragma unroll
        for (int k = 0; k < 8; ++k) {
            float v = t[tx + 32 * k][c];
            s += v; s2 += v * v;
        }
#pragma unroll
        for (int off = 16; off > 0; off >>= 1) {
            s += __shfl_xor_sync(0xffffffffu, s, off);
            s2 += __shfl_xor_sync(0xffffffffu, s2, off);
        }
        if (tx == 0) {
            float mu = s * (1.0f / Hn);
            float var = s2 * (1.0f / Hn) - mu * mu;
            mu_s[c] = mu;
            rs_s[c] = rsqrtf(var + 1e-5f);
        }
    }
    __syncthreads();

    if (!last) {
        for (int oo = 0; oo < Hn; oo += 8) {
            int o = oo + ty;
            float v = (t[o][tx] - mu_s[tx]) * rs_s[tx] * lnw[o] + lnb[o];
            Hb[(size_t)o * Ln + l0 + tx] = v;
        }
    } else {
        // final layer: h never read again except for mean-pool -> emit partials
        for (int oo = 0; oo < Hn; oo += 8) {
            int o = oo + ty;
            float v = (t[o][tx] - mu_s[tx]) * rs_s[tx] * lnw[o] + lnb[o];
#pragma unroll
            for (int off = 16; off > 0; off >>= 1)
                v += __shfl_xor_sync(0xffffffffu, v, off);
            if (tx == 0)
                g_poolpart[((size_t)b * Hn + o) * (Ln / 32) + blockIdx.x] = v;
        }
    }
}

// ---------------- 5. pool reduce: sum 128 partials per (b,h) ----------------
__global__ void pool_reduce_kernel() {
    int row = blockIdx.x;  // b*H+h
    int tid = threadIdx.x; // 128
    __shared__ float red[128];
    red[tid] = g_poolpart[(size_t)row * (Ln / 32) + tid];
    __syncthreads();
    for (int off = 64; off > 0; off >>= 1) {
        if (tid < off) red[tid] += red[tid + off];
        __syncthreads();
    }
    if (tid == 0) g_pool[row] = red[0] * (1.0f / Ln);
}

// ---------------- 6. decoder ----------------
__global__ void decode_kernel(const float* __restrict__ dec_w,
                              const float* __restrict__ dec_b,
                              float* __restrict__ out) {
    int idx = threadIdx.x;      // 256 = B*DOUT
    int b = idx >> 3, d = idx & 7;
    float s = dec_b[d];
    for (int h = 0; h < Hn; ++h)
        s += g_pool[b * Hn + h] * dec_w[d * Hn + h];
    out[idx] = sigmoidf_(s);
}

// ---------------- launch ----------------
extern "C" void kernel_launch(void* const* d_in, const int* in_sizes, int n_in,
                              void* d_out, int out_size) {
    const float* x          = (const float*)d_in[0];
    const float* enc_w      = (const float*)d_in[1];
    const float* enc_b      = (const float*)d_in[2];
    const float* log_dt     = (const float*)d_in[3];
    const float* C_re       = (const float*)d_in[4];
    const float* C_im       = (const float*)d_in[5];
    const float* log_A_real = (const float*)d_in[6];
    const float* A_imag     = (const float*)d_in[7];
    const float* D          = (const float*)d_in[8];
    const float* out_w      = (const float*)d_in[9];
    const float* out_b      = (const float*)d_in[10];
    const float* ln_w       = (const float*)d_in[11];
    const float* ln_b       = (const float*)d_in[12];
    const float* dec_w      = (const float*)d_in[13];
    const float* dec_b      = (const float*)d_in[14];
    float* out = (float*)d_out;

    precompute_kernel<<<(NLn * Hn * N2n + 255) / 256, 256>>>(log_dt, C_re, C_im,
                                                             log_A_real, A_imag);
    precompute2_kernel<<<(NLn * Hn) / 8, 256>>>(D);
    fragmat_kernel<<<(NLn * Hn * 1024 + 255) / 256, 256>>>();
    wfrag_kernel<<<(NLn * 512 * 256 + 255) / 256, 256>>>(out_w);

    dim3 ggrid(Ln / 128, 512 / 128, Bn);
    dim3 egrid(Ln / 32, Bn);

    for (int i = 0; i < NLn; ++i) {
        scan_tc_kernel<<<Hn * 8, 128>>>(x, enc_w, enc_b, i);
        gemm_tc_kernel<<<ggrid, 256>>>(out_b, i);
        glu_ln_kernel<<<egrid, 256>>>(ln_w, ln_b, i, i == NLn - 1);
    }

    pool_reduce_kernel<<<Bn * Hn, 128>>>();
    decode_kernel<<<1, 256>>>(dec_w, dec_b, out);
}

// round 15
// speedup vs baseline: 1.5023x; 1.0522x over previous
#include <cuda_runtime.h>
#include <cuda_bf16.h>
#include <math.h>
#include <stdint.h>

// Problem constants
#define Bn   32
#define Ln   4096
#define Hn   256
#define N2n  32
#define NLn  4
#define DOUTn 8

// ---------------- scratch (device globals; no allocation allowed) ----------------
__device__ float    g_h[(size_t)Bn * Hn * Ln];     // 128 MB  current hidden (B,H,L)
__device__ uint32_t g_y[(size_t)Bn * Hn * Ln];     // 128 MB  tf32 bits of gelu(ssm) (B,H,L)
__device__ float    g_z[(size_t)Bn * 2 * Hn * Ln]; // 256 MB  GEMM output (B,2H,L)
__device__ float    g_par[NLn * 4 * Hn * N2n];     // w_re,w_im,cd_re,cd_im (2x folded)
__device__ uint32_t g_wfrag[NLn * 512 * 256];      // W as tf32 bits, MMA-fragment order
__device__ float    g_pool[Bn * Hn];
__device__ float    g_poolpart[Bn * Hn * (Ln / 32)];  // 4 MB partial pool sums
// Toeplitz-scan matrices, per (layer,h): 32x32 each, row-major (fp32 staging)
__device__ float    g_T  [NLn * Hn * 1024];
__device__ float    g_M1 [NLn * Hn * 1024];
__device__ float    g_M2 [NLn * Hn * 1024];
__device__ float    g_Gre[NLn * Hn * 1024];
__device__ float    g_Gim[NLn * Hn * 1024];
// fragment-ordered tf32 versions: [mt(2)][k8(4)][lane(32)][4]
__device__ uint32_t g_Tf  [NLn * Hn * 1024];
__device__ uint32_t g_M1f [NLn * Hn * 1024];
__device__ uint32_t g_M2f [NLn * Hn * 1024];
__device__ uint32_t g_Grf [NLn * Hn * 1024];
__device__ uint32_t g_Gif [NLn * Hn * 1024];
__device__ float    g_w32re[NLn * Hn * 32];
__device__ float    g_w32im[NLn * Hn * 32];

// ---------------- helpers ----------------
__device__ __forceinline__ float tanh_fast(float x) {
    float r;
    asm("tanh.approx.f32 %0, %1;" : "=f"(r) : "f"(x));
    return r;
}
__device__ __forceinline__ float gelu_tanh(float x) {
    float x3 = x * x * x;
    float t = tanh_fast(0.7978845608028654f * (x + 0.044715f * x3));
    return 0.5f * x * (1.0f + t);
}
// sigmoid via ex2.approx + rcp.approx (few instrs; err ~2^-11, below tf32 noise)
__device__ __forceinline__ float sigmoidf_(float x) {
    float e, r;
    asm("ex2.approx.f32 %0, %1;" : "=f"(e) : "f"(-1.4426950408889634f * x));
    asm("rcp.approx.f32 %0, %1;" : "=f"(r) : "f"(1.0f + e));
    return r;
}
__device__ __forceinline__ uint32_t to_tf32(float x) {
    uint32_t r;
    asm("cvt.rna.tf32.f32 %0, %1;" : "=r"(r) : "f"(x));
    return r;
}
__device__ __forceinline__ void cp_async16(void* smem_dst, const void* gsrc) {
    uint32_t s = (uint32_t)__cvta_generic_to_shared(smem_dst);
    asm volatile("cp.async.cg.shared.global [%0], [%1], 16;\n" :: "r"(s), "l"(gsrc));
}
#define CP_COMMIT() asm volatile("cp.async.commit_group;\n" ::: "memory")
#define CP_WAIT1()  asm volatile("cp.async.wait_group 1;\n" ::: "memory")
#define CP_WAIT0()  asm volatile("cp.async.wait_group 0;\n" ::: "memory")

// mma.sync m16n8k8 tf32: D = A@B + D   (A,B as raw b32 tf32 bit patterns)
__device__ __forceinline__ void mma_tf32(float (&d)[4], const uint4& a, const uint2& b) {
    asm volatile(
        "mma.sync.aligned.m16n8k8.row.col.f32.tf32.tf32.f32 "
        "{%0,%1,%2,%3}, {%4,%5,%6,%7}, {%8,%9}, {%0,%1,%2,%3};\n"
        : "+f"(d[0]), "+f"(d[1]), "+f"(d[2]), "+f"(d[3])
        : "r"(a.x), "r"(a.y), "r"(a.z), "r"(a.w), "r"(b.x), "r"(b.y));
}

// ---------------- 0a. precompute discretized SSM params ----------------
__global__ void precompute_kernel(const float* __restrict__ log_dt,
                                  const float* __restrict__ C_re,
                                  const float* __restrict__ C_im,
                                  const float* __restrict__ log_A_real,
                                  const float* __restrict__ A_imag) {
    int idx = blockIdx.x * blockDim.x + threadIdx.x;      // NL*H*N2
    if (idx >= NLn * Hn * N2n) return;
    int i = idx / (Hn * N2n);
    int rem = idx % (Hn * N2n);
    int h = rem / N2n;

    float dt = expf(log_dt[i * Hn + h]);
    float Are = -expf(log_A_real[idx]);
    float Aim = A_imag[idx];
    float dre = Are * dt, dim = Aim * dt;
    float e = expf(dre);
    float w_re = e * cosf(dim);
    float w_im = e * sinf(dim);
    float inv = 1.0f / (Are * Are + Aim * Aim);
    float nre = w_re - 1.0f, nim = w_im;
    float fre = (nre * Are + nim * Aim) * inv;
    float fim = (nim * Are - nre * Aim) * inv;
    float cre = C_re[idx], cim = C_im[idx];
    float cd_re = cre * fre - cim * fim;
    float cd_im = cre * fim + cim * fre;

    int base = ((i * 4 + 0) * Hn + h) * N2n + (idx % N2n);
    int stride = Hn * N2n;
    g_par[base + 0 * stride] = w_re;
    g_par[base + 1 * stride] = w_im;
    g_par[base + 2 * stride] = 2.0f * cd_re;   // fold the 2x into C
    g_par[base + 3 * stride] = 2.0f * cd_im;
}

// ---------------- 0b. build Toeplitz-scan matrices per (layer,h) ----------------
__global__ __launch_bounds__(256) void precompute2_kernel(const float* __restrict__ Dmat) {
    __shared__ float kbuf[8][33];
    int warp = threadIdx.x >> 5, lane = threadIdx.x & 31;
    int idx = blockIdx.x * 8 + warp;           // 0..NL*Hn-1
    if (idx >= NLn * Hn) return;
    int l = idx >> 8, h = idx & 255;

    int pstride = Hn * N2n;
    int pbase = ((l * 4) * Hn + h) * N2n + lane;
    float wre = g_par[pbase + 0 * pstride];
    float wim = g_par[pbase + 1 * pstride];
    float cre = g_par[pbase + 2 * pstride];    // 2*Cd
    float cim = g_par[pbase + 3 * pstride];
    float Dh = Dmat[l * Hn + h];

    size_t mbase = (size_t)idx * 1024;

    float pre = 1.0f, pim = 0.0f;              // w^0
    for (int d = 0; d <= 32; ++d) {
        float m1 = cre * pre - cim * pim;        // Re(Cd w^d)
        float m2 = -(cre * pim + cim * pre);     // -Im(Cd w^d)
        if (d >= 1) {
            g_M1[mbase + (size_t)(d - 1) * 32 + lane] = m1;   // M1[t=d-1][n]
            g_M2[mbase + (size_t)(d - 1) * 32 + lane] = m2;
        }
        if (d < 32) {
            float kd = m1;
#pragma unroll
            for (int off = 16; off > 0; off >>= 1)
                kd += __shfl_xor_sync(0xffffffffu, kd, off);
            if (lane == 0) kbuf[warp][d] = kd;
            g_Gre[mbase + (size_t)lane * 32 + (31 - d)] = pre;
            g_Gim[mbase + (size_t)lane * 32 + (31 - d)] = pim;
        }
        if (d == 32) {
            g_w32re[(size_t)idx * 32 + lane] = pre;
            g_w32im[(size_t)idx * 32 + lane] = pim;
        }
        float npre = pre * wre - pim * wim;
        float npim = pre * wim + pim * wre;
        pre = npre; pim = npim;
    }
    __syncwarp();
    for (int e = lane; e < 1024; e += 32) {
        int t = e >> 5, s = e & 31;
        float v = 0.0f;
        if (t > s) v = kbuf[warp][t - s];
        else if (t == s) v = kbuf[warp][0] + Dh;
        g_T[mbase + e] = v;
    }
}

// ---------------- 0c. fragment-order the scan matrices (tf32 bits) ----------------
__global__ void fragmat_kernel() {
    int idx = blockIdx.x * blockDim.x + threadIdx.x;   // NL*Hn*1024
    if (idx >= NLn * Hn * 1024) return;
    int blk = idx >> 10;           // (layer,h)
    int e = idx & 1023;
    int t = e >> 5, s = e & 31;
    int mt = t >> 4;
    int g = t & 7;
    int r8 = (t >> 3) & 1;
    int k8 = s >> 3;
    int tig = s & 3;
    int half = (s >> 2) & 1;
    int lane = 4 * g + tig;
    int i = r8 + 2 * half;
    size_t src = (size_t)blk * 1024 + e;
    size_t dst = (size_t)blk * 1024 + (((mt * 4 + k8) * 32 + lane) * 4 + i);
    g_Tf [dst] = to_tf32(g_T  [src]);
    g_M1f[dst] = to_tf32(g_M1 [src]);
    g_M2f[dst] = to_tf32(g_M2 [src]);
    g_Grf[dst] = to_tf32(g_Gre[src]);
    g_Gif[dst] = to_tf32(g_Gim[src]);
}

// ---------------- 0d. pre-permute W into tf32 MMA-fragment order ----------------
__global__ void wfrag_kernel(const float* __restrict__ out_w) {
    int idx = blockIdx.x * blockDim.x + threadIdx.x;    // NL*512*256
    if (idx >= NLn * 512 * 256) return;
    int layer = idx / (512 * 256);
    int rem = idx % (512 * 256);
    int m = rem / 256;
    int k = rem % 256;
    uint32_t val = to_tf32(out_w[idx]);

    int kc = k >> 4;
    int kk = (k >> 3) & 1;
    int tig = k & 3;
    int half = (k >> 2) & 1;
    int mt = m >> 4;
    int g = m & 7;
    int r8 = (m >> 3) & 1;
    int lane = 4 * g + tig;
    int i4 = r8 + 2 * half;
    int dst = (((kc * 32 + mt) * 2 + kk) * 32 + lane) * 4 + i4;
    g_wfrag[layer * 131072 + dst] = val;
}

// ---------------- 2. Toeplitz-chunk SSM scan on tensor cores ----------------
// Block: one h, 4 warps = 4 b's. grid = 256h x 8 b-groups = 2048 blocks, 128 thr.
__global__ __launch_bounds__(128) void scan_tc_kernel(const float* __restrict__ x,
                                                      const float* __restrict__ enc_w,
                                                      const float* __restrict__ enc_b,
                                                      int layer) {
    __shared__ uint32_t Tf [1024];       // frag order: [(mt*4+k8)*32+lane][4]
    __shared__ uint32_t M1f[1024];
    __shared__ uint32_t M2f[1024];
    __shared__ uint32_t Grf[1024];
    __shared__ uint32_t Gif[1024];
    __shared__ uint32_t Us [4][32][9];   // u tile tf32 [s][c]
    __shared__ float    Sre[4][32][9];   // S output / reused as y tile
    __shared__ float    Sim[4][32][9];
    __shared__ uint32_t Pre[4][32][9];   // s_prev tf32 bits [n][c]
    __shared__ uint32_t Pim[4][32][9];

    int tid = threadIdx.x;
    int warp = tid >> 5, lane = tid & 31;
    int g = lane >> 2, tig = lane & 3;
    int h = blockIdx.x >> 3;
    int b = (blockIdx.x & 7) * 4 + warp;

    // load per-h frag matrices: straight uint4 copies (2 per thread per matrix)
    size_t fb = (size_t)(layer * Hn + h) * 1024;
    {
        const uint4* s0 = reinterpret_cast<const uint4*>(g_Tf  + fb);
        const uint4* s1 = reinterpret_cast<const uint4*>(g_M1f + fb);
        const uint4* s2 = reinterpret_cast<const uint4*>(g_M2f + fb);
        const uint4* s3 = reinterpret_cast<const uint4*>(g_Grf + fb);
        const uint4* s4 = reinterpret_cast<const uint4*>(g_Gif + fb);
#pragma unroll
        for (int e = 0; e < 2; ++e) {
            int i4 = tid + e * 128;
            reinterpret_cast<uint4*>(Tf )[i4] = s0[i4];
            reinterpret_cast<uint4*>(M1f)[i4] = s1[i4];
            reinterpret_cast<uint4*>(M2f)[i4] = s2[i4];
            reinterpret_cast<uint4*>(Grf)[i4] = s3[i4];
            reinterpret_cast<uint4*>(Gif)[i4] = s4[i4];
        }
    }
    __syncthreads();

    float w32re_ = g_w32re[(size_t)(layer * Hn + h) * 32 + lane];
    float w32im_ = g_w32im[(size_t)(layer * Hn + h) * 32 + lane];

    size_t rowoff = ((size_t)b * Hn + h) * Ln;
    float* hrow = g_h + rowoff;
    uint32_t* yrow = g_y + rowoff;
    const float* xrow = x + (size_t)b * Ln;
    bool l0fuse = (layer == 0);
    float ew = l0fuse ? enc_w[h] : 0.0f;
    float eb = l0fuse ? enc_b[h] : 0.0f;

    float sre = 0.0f, sim = 0.0f;

    for (int gr = 0; gr < 16; ++gr) {
        int base_l = gr * 256;
        // ---- fill u tile [s=lane][c=i] ----
        if (l0fuse) {
#pragma unroll
            for (int i = 0; i < 8; ++i) {
                float v = fmaf(xrow[base_l + i * 32 + lane], ew, eb);
                hrow[base_l + i * 32 + lane] = v;
                Us[warp][lane][i] = to_tf32(v);
            }
        } else {
#pragma unroll
            for (int i = 0; i < 8; ++i)
                Us[warp][lane][i] = to_tf32(hrow[base_l + i * 32 + lane]);
        }
        __syncwarp();

        // ---- B fragments from u tile ----
        uint2 bu[4];
#pragma unroll
        for (int k8 = 0; k8 < 4; ++k8) {
            bu[k8].x = Us[warp][k8 * 8 + tig][g];
            bu[k8].y = Us[warp][k8 * 8 + tig + 4][g];
        }

        // ---- S = Gre@U, Gim@U ----
        float fre[2][4], fim[2][4];
#pragma unroll
        for (int mt = 0; mt < 2; ++mt)
#pragma unroll
            for (int r = 0; r < 4; ++r) { fre[mt][r] = 0.0f; fim[mt][r] = 0.0f; }
#pragma unroll
        for (int mt = 0; mt < 2; ++mt) {
#pragma unroll
            for (int k8 = 0; k8 < 4; ++k8) {
                int fo = ((mt * 4 + k8) * 32 + lane) * 4;
                mma_tf32(fre[mt], *reinterpret_cast<const uint4*>(&Grf[fo]), bu[k8]);
                mma_tf32(fim[mt], *reinterpret_cast<const uint4*>(&Gif[fo]), bu[k8]);
            }
        }
#pragma unroll
        for (int mt = 0; mt < 2; ++mt) {
            int mr = mt * 16;
            Sre[warp][mr + g][2 * tig]     = fre[mt][0];
            Sre[warp][mr + g][2 * tig + 1] = fre[mt][1];
            Sre[warp][mr + g + 8][2 * tig]     = fre[mt][2];
            Sre[warp][mr + g + 8][2 * tig + 1] = fre[mt][3];
            Sim[warp][mr + g][2 * tig]     = fim[mt][0];
            Sim[warp][mr + g][2 * tig + 1] = fim[mt][1];
            Sim[warp][mr + g + 8][2 * tig]     = fim[mt][2];
            Sim[warp][mr + g + 8][2 * tig + 1] = fim[mt][3];
        }
        __syncwarp();

        // ---- sequential scan over 8 chunks (lane = state n) ----
#pragma unroll
        for (int c = 0; c < 8; ++c) {
            Pre[warp][lane][c] = to_tf32(sre);
            Pim[warp][lane][c] = to_tf32(sim);
            float S_re = Sre[warp][lane][c];
            float S_im = Sim[warp][lane][c];
            float nre = fmaf(w32re_, sre, fmaf(-w32im_, sim, S_re));
            float nim = fmaf(w32re_, sim, fmaf(w32im_, sre, S_im));
            sre = nre; sim = nim;
        }
        __syncwarp();

        // ---- Y = T@U + M1@Sprev_re + M2@Sprev_im ----
        float yf[2][4];
#pragma unroll
        for (int mt = 0; mt < 2; ++mt)
#pragma unroll
            for (int r = 0; r < 4; ++r) yf[mt][r] = 0.0f;
        uint2 bp[4], bq[4];
#pragma unroll
        for (int k8 = 0; k8 < 4; ++k8) {
            bp[k8].x = Pre[warp][k8 * 8 + tig][g];
            bp[k8].y = Pre[warp][k8 * 8 + tig + 4][g];
            bq[k8].x = Pim[warp][k8 * 8 + tig][g];
            bq[k8].y = Pim[warp][k8 * 8 + tig + 4][g];
        }
#pragma unroll
        for (int mt = 0; mt < 2; ++mt) {
#pragma unroll
            for (int k8 = 0; k8 < 4; ++k8) {
                int fo = ((mt * 4 + k8) * 32 + lane) * 4;
                mma_tf32(yf[mt], *reinterpret_cast<const uint4*>(&Tf [fo]), bu[k8]);
                mma_tf32(yf[mt], *reinterpret_cast<const uint4*>(&M1f[fo]), bp[k8]);
                mma_tf32(yf[mt], *reinterpret_cast<const uint4*>(&M2f[fo]), bq[k8]);
            }
        }
        // ---- stage Y to smem (reuse Sre), then gelu + store ----
#pragma unroll
        for (int mt = 0; mt < 2; ++mt) {
            int mr = mt * 16;
            Sre[warp][mr + g][2 * tig]     = yf[mt][0];
            Sre[warp][mr + g][2 * tig + 1] = yf[mt][1];
            Sre[warp][mr + g + 8][2 * tig]     = yf[mt][2];
            Sre[warp][mr + g + 8][2 * tig + 1] = yf[mt][3];
        }
        __syncwarp();
#pragma unroll
        for (int i = 0; i < 8; ++i) {
            float v = Sre[warp][lane][i];      // y[t=lane][c=i]
            yrow[base_l + i * 32 + lane] = to_tf32(gelu_tanh(v));
        }
        __syncwarp();
    }
}

// ---------------- 3. tf32 GEMM: cp.async 2-stage pipeline, fragment-ordered A ----
__global__ __launch_bounds__(256) void gemm_tc_kernel(const float* __restrict__ out_b,
                                                      int layer) {
    __shared__ uint32_t As[2][2048];      // per-kc A chunk (frag order), 2 stages
    __shared__ uint32_t Bs[2][16][132];   // per-kc B chunk [k][n] pad 132, 2 stages

    int b = blockIdx.z;
    const uint32_t* Yb = g_y + (size_t)b * Hn * Ln;
    float* Z = g_z + (size_t)b * 2 * Hn * Ln;
    const uint32_t* Wf = g_wfrag + layer * 131072;
    const float* obl = out_b + layer * 2 * Hn;

    int n0 = blockIdx.x * 128;
    int m0 = blockIdx.y * 128;
    int mt0 = m0 >> 4;

    int tid = threadIdx.x;
    int warp = tid >> 5, lane = tid & 31;
    int wm = warp >> 2;
    int wn = warp & 3;
    int g = lane >> 2, tig = lane & 3;

    // B copy indices (fixed per thread)
    int br0 = tid >> 5, bc0 = (tid & 31) * 4;          // j=0
    int br1 = (tid + 256) >> 5, bc1 = bc0;             // j=1 (row +8)

    float acc[4][4][4];
#pragma unroll
    for (int mt = 0; mt < 4; ++mt)
#pragma unroll
        for (int nt = 0; nt < 4; ++nt)
#pragma unroll
            for (int r = 0; r < 4; ++r) acc[mt][nt][r] = 0.0f;

    // async tile loader: A 2 x 16B/thread, B 2 x 16B/thread
    auto load_tile = [&](int kc, int s) {
        const uint4* srcA = reinterpret_cast<const uint4*>(Wf + (kc * 32 + mt0) * 256);
        cp_async16(&reinterpret_cast<uint4*>(As[s])[tid], srcA + tid);
        cp_async16(&reinterpret_cast<uint4*>(As[s])[tid + 256], srcA + tid + 256);
        cp_async16(&Bs[s][br0][bc0], &Yb[(size_t)(kc * 16 + br0) * Ln + n0 + bc0]);
        cp_async16(&Bs[s][br1][bc1], &Yb[(size_t)(kc * 16 + br1) * Ln + n0 + bc1]);
    };

    load_tile(0, 0); CP_COMMIT();
    load_tile(1, 1); CP_COMMIT();

    for (int kc = 0; kc < 16; ++kc) {
        if (kc < 14) CP_WAIT1(); else CP_WAIT0();
        __syncthreads();
        int s = kc & 1;

#pragma unroll
        for (int kk = 0; kk < 2; ++kk) {
            int k8 = kk * 8;
            uint4 afr[4];
#pragma unroll
            for (int mt = 0; mt < 4; ++mt)
                afr[mt] = *reinterpret_cast<const uint4*>(
                    &As[s][(((wm * 4 + mt) * 2 + kk) * 32 + lane) * 4]);
            uint2 bfr[4];
#pragma unroll
            for (int nt = 0; nt < 4; ++nt) {
                int ncol = wn * 32 + nt * 8;
                bfr[nt].x = Bs[s][k8 + tig][ncol + g];
                bfr[nt].y = Bs[s][k8 + tig + 4][ncol + g];
            }
#pragma unroll
            for (int mt = 0; mt < 4; ++mt)
#pragma unroll
                for (int nt = 0; nt < 4; ++nt)
                    mma_tf32(acc[mt][nt], afr[mt], bfr[nt]);
        }
        __syncthreads();
        if (kc + 2 < 16) { load_tile(kc + 2, s); CP_COMMIT(); }
    }

#pragma unroll
    for (int mt = 0; mt < 4; ++mt) {
        int m = m0 + wm * 64 + mt * 16 + g;
        float bias0 = obl[m];
        float bias1 = obl[m + 8];
#pragma unroll
        for (int nt = 0; nt < 4; ++nt) {
            int n = n0 + wn * 32 + nt * 8 + 2 * tig;
            float2 v0 = make_float2(acc[mt][nt][0] + bias0, acc[mt][nt][1] + bias0);
            float2 v1 = make_float2(acc[mt][nt][2] + bias1, acc[mt][nt][3] + bias1);
            *reinterpret_cast<float2*>(&Z[(size_t)m * Ln + n]) = v0;
            *reinterpret_cast<float2*>(&Z[(size_t)(m + 8) * Ln + n]) = v1;
        }
    }
}

// ---------------- 4. GLU + residual + LayerNorm (last layer: emit pool partials) --
__global__ __launch_bounds__(256) void glu_ln_kernel(const float* __restrict__ ln_w_all,
                                                     const float* __restrict__ ln_b_all,
                                                     int layer, int last) {
    int b = blockIdx.y;
    int l0 = blockIdx.x * 32;
    const float* Z = g_z + (size_t)b * 2 * Hn * Ln;
    float* Hb = g_h + (size_t)b * Hn * Ln;
    const float* lnw = ln_w_all + layer * Hn;
    const float* lnb = ln_b_all + layer * Hn;

    __shared__ float t[Hn][33];
    __shared__ float mu_s[32], rs_s[32];

    int tx = threadIdx.x & 31;
    int ty = threadIdx.x >> 5;

    for (int oo = 0; oo < Hn; oo += 8) {
        int o = oo + ty;
        float a = Z[(size_t)o * Ln + l0 + tx];
        float g = Z[(size_t)(o + Hn) * Ln + l0 + tx];
        float hold = Hb[(size_t)o * Ln + l0 + tx];
        t[o][tx] = a * sigmoidf_(g) + hold;
    }
    __syncthreads();

    for (int c = ty; c < 32; c += 8) {
        float s = 0.0f, s2 = 0.0f;
#pragma unroll
        for (int k = 0; k < 8; ++k) {
            float v = t[tx + 32 * k][c];
            s += v; s2 += v * v;
        }
#pragma unroll
        for (int off = 16; off > 0; off >>= 1) {
            s += __shfl_xor_sync(0xffffffffu, s, off);
            s2 += __shfl_xor_sync(0xffffffffu, s2, off);
        }
        if (tx == 0) {
            float mu = s * (1.0f / Hn);
            float var = s2 * (1.0f / Hn) - mu * mu;
            mu_s[c] = mu;
            rs_s[c] = rsqrtf(var + 1e-5f);
        }
    }
    __syncthreads();

    if (!last) {
        for (int oo = 0; oo < Hn; oo += 8) {
            int o = oo + ty;
            float v = (t[o][tx] - mu_s[tx]) * rs_s[tx] * lnw[o] + lnb[o];
            Hb[(size_t)o * Ln + l0 + tx] = v;
        }
    } else {
        // final layer: h never read again except for mean-pool -> emit partials
        for (int oo = 0; oo < Hn; oo += 8) {
            int o = oo + ty;
            float v = (t[o][tx] - mu_s[tx]) * rs_s[tx] * lnw[o] + lnb[o];
#pragma unroll
            for (int off = 16; off > 0; off >>= 1)
                v += __shfl_xor_sync(0xffffffffu, v, off);
            if (tx == 0)
                g_poolpart[((size_t)b * Hn + o) * (Ln / 32) + blockIdx.x] = v;
        }
    }
}

// ---------------- 5. pool reduce: sum 128 partials per (b,h) ----------------
__global__ void pool_reduce_kernel() {
    int row = blockIdx.x;  // b*H+h
    int tid = threadIdx.x; // 128
    __shared__ float red[128];
    red[tid] = g_poolpart[(size_t)row * (Ln / 32) + tid];
    __syncthreads();
    for (int off = 64; off > 0; off >>= 1) {
        if (tid < off) red[tid] += red[tid + off];
        __syncthreads();
    }
    if (tid == 0) g_pool[row] = red[0] * (1.0f / Ln);
}

// ---------------- 6. decoder ----------------
__global__ void decode_kernel(const float* __restrict__ dec_w,
                              const float* __restrict__ dec_b,
                              float* __restrict__ out) {
    int idx = threadIdx.x;      // 256 = B*DOUT
    int b = idx >> 3, d = idx & 7;
    float s = dec_b[d];
    for (int h = 0; h < Hn; ++h)
        s += g_pool[b * Hn + h] * dec_w[d * Hn + h];
    out[idx] = 1.0f / (1.0f + expf(-s));   // keep accurate sigmoid at the output
}

// ---------------- launch ----------------
extern "C" void kernel_launch(void* const* d_in, const int* in_sizes, int n_in,
                              void* d_out, int out_size) {
    const float* x          = (const float*)d_in[0];
    const float* enc_w      = (const float*)d_in[1];
    const float* enc_b      = (const float*)d_in[2];
    const float* log_dt     = (const float*)d_in[3];
    const float* C_re       = (const float*)d_in[4];
    const float* C_im       = (const float*)d_in[5];
    const float* log_A_real = (const float*)d_in[6];
    const float* A_imag     = (const float*)d_in[7];
    const float* D          = (const float*)d_in[8];
    const float* out_w      = (const float*)d_in[9];
    const float* out_b      = (const float*)d_in[10];
    const float* ln_w       = (const float*)d_in[11];
    const float* ln_b       = (const float*)d_in[12];
    const float* dec_w      = (const float*)d_in[13];
    const float* dec_b      = (const float*)d_in[14];
    float* out = (float*)d_out;

    precompute_kernel<<<(NLn * Hn * N2n + 255) / 256, 256>>>(log_dt, C_re, C_im,
                                                             log_A_real, A_imag);
    precompute2_kernel<<<(NLn * Hn) / 8, 256>>>(D);
    fragmat_kernel<<<(NLn * Hn * 1024 + 255) / 256, 256>>>();
    wfrag_kernel<<<(NLn * 512 * 256 + 255) / 256, 256>>>(out_w);

    dim3 ggrid(Ln / 128, 512 / 128, Bn);
    dim3 egrid(Ln / 32, Bn);

    for (int i = 0; i < NLn; ++i) {
        scan_tc_kernel<<<Hn * 8, 128>>>(x, enc_w, enc_b, i);
        gemm_tc_kernel<<<ggrid, 256>>>(out_b, i);
        glu_ln_kernel<<<egrid, 256>>>(ln_w, ln_b, i, i == NLn - 1);
    }

    pool_reduce_kernel<<<Bn * Hn, 128>>>();
    decode_kernel<<<1, 256>>>(dec_w, dec_b, out);
}